// round 4
// baseline (speedup 1.0000x reference)
#include <cuda_runtime.h>
#include <cuda_bf16.h>
#include <cstdint>

#define BATCH 8
#define SEQ   4096
#define HDIM  512
#define NROWS (BATCH * SEQ)   // 32768
#define NHEAD 64
#define TLEN  64

#define BM 128
#define BN 256
#define BK 32
#define NCHUNK (HDIM / BK)    // 16

#define ROWB 80               // smem row stride bytes (32 bf16 data + pad)

// smem layout (bytes from dynamic base)
#define SMP_PRM   0
#define SMP_A     512                          // [buf][split] 4 x 10240
#define A_BUF_STRIDE 20480
#define SMP_B     (512 + 40960)                // [buf][split] 4 x 20480
#define B_BUF_STRIDE 40960
#define SMEM_REQ  (512 + 40960 + 81920)        // 123392

// ---------------- scratch (device globals; allocation-free) ----------------
__device__ float g_Q[NROWS * HDIM];
__device__ float g_K[NROWS * HDIM];
__device__ float g_V[NROWS * HDIM];
__device__ __nv_bfloat16 g_xh[NROWS * HDIM];
__device__ __nv_bfloat16 g_xl[NROWS * HDIM];
__device__ __nv_bfloat16 g_Wh[4 * HDIM * HDIM];
__device__ __nv_bfloat16 g_Wl[4 * HDIM * HDIM];

// ---------------- helpers ----------------
__device__ __forceinline__ uint32_t smem_to_u32(const void* p) {
    uint32_t a;
    asm("{ .reg .u64 t; cvta.to.shared.u64 t, %1; cvt.u32.u64 %0, t; }"
        : "=r"(a) : "l"(p));
    return a;
}
__device__ __forceinline__ void cp16(uint32_t dst, const void* src) {
    asm volatile("cp.async.cg.shared.global [%0], [%1], 16;"
                 :: "r"(dst), "l"(src) : "memory");
}
__device__ __forceinline__ void cp_commit() {
    asm volatile("cp.async.commit_group;" ::: "memory");
}
__device__ __forceinline__ void cp_wait1() {
    asm volatile("cp.async.wait_group 1;" ::: "memory");
}
__device__ __forceinline__ void cp_wait0() {
    asm volatile("cp.async.wait_group 0;" ::: "memory");
}
__device__ __forceinline__ void ldsm4(uint32_t* r, uint32_t addr) {
    asm volatile("ldmatrix.sync.aligned.m8n8.x4.shared.b16 {%0,%1,%2,%3}, [%4];"
                 : "=r"(r[0]), "=r"(r[1]), "=r"(r[2]), "=r"(r[3]) : "r"(addr));
}
__device__ __forceinline__ void mma16816(float* d, const uint32_t* a,
                                         const uint32_t b0, const uint32_t b1) {
    asm volatile(
        "mma.sync.aligned.m16n8k16.row.col.f32.bf16.bf16.f32 "
        "{%0,%1,%2,%3}, {%4,%5,%6,%7}, {%8,%9}, {%0,%1,%2,%3};"
        : "+f"(d[0]), "+f"(d[1]), "+f"(d[2]), "+f"(d[3])
        : "r"(a[0]), "r"(a[1]), "r"(a[2]), "r"(a[3]), "r"(b0), "r"(b1));
}

// ---------------------------------------------------------------------------
// fp32 -> bf16 hi/lo split conversion
// ---------------------------------------------------------------------------
__global__ void __launch_bounds__(256) conv_kernel(
    const float* __restrict__ src, __nv_bfloat16* __restrict__ h,
    __nv_bfloat16* __restrict__ l, int n4)
{
    int i = blockIdx.x * 256 + threadIdx.x;
    if (i >= n4) return;
    float4 v = ((const float4*)src)[i];
    __nv_bfloat16 hx = __float2bfloat16(v.x);
    __nv_bfloat16 hy = __float2bfloat16(v.y);
    __nv_bfloat16 hz = __float2bfloat16(v.z);
    __nv_bfloat16 hw = __float2bfloat16(v.w);
    __nv_bfloat16 lx = __float2bfloat16(v.x - __bfloat162float(hx));
    __nv_bfloat16 ly = __float2bfloat16(v.y - __bfloat162float(hy));
    __nv_bfloat16 lz = __float2bfloat16(v.z - __bfloat162float(hz));
    __nv_bfloat16 lw = __float2bfloat16(v.w - __bfloat162float(hw));
    __nv_bfloat162* hp = (__nv_bfloat162*)h;
    __nv_bfloat162* lp = (__nv_bfloat162*)l;
    __nv_bfloat162 t;
    t.x = hx; t.y = hy; hp[2 * i]     = t;
    t.x = hz; t.y = hw; hp[2 * i + 1] = t;
    t.x = lx; t.y = ly; lp[2 * i]     = t;
    t.x = lz; t.y = lw; lp[2 * i + 1] = t;
}

// ---------------------------------------------------------------------------
// Split-bf16 GEMM via mma.sync: out[m,n] = sum_k A[rowmap(m),k]*W[n,k] + bias[n]
// D ≈ Ah·Bh + Ah·Bl + Al·Bh (fp32 accum). BM=128, BN=256, BK=32.
// 8 warps (2m x 4n), warp tile 64x64 — halves LDSM per MMA vs 64x32.
// ---------------------------------------------------------------------------
__global__ void __launch_bounds__(256, 1) mma_gemm_kernel(
    const __nv_bfloat16* __restrict__ Ah, const __nv_bfloat16* __restrict__ Al,
    const __nv_bfloat16* __restrict__ Bh, const __nv_bfloat16* __restrict__ Bl,
    const float* __restrict__ bias, float* __restrict__ out,
    const int* __restrict__ perm, int use_perm)
{
    extern __shared__ char smem[];
    const uint32_t sb = smem_to_u32(smem);
    int* prm = (int*)(smem + SMP_PRM);

    const int tid = threadIdx.x;
    const int lid = tid & 31;
    const int wid = tid >> 5;
    const int wm  = wid & 1;    // 0..1  (m)
    const int wn  = wid >> 1;   // 0..3  (n)

    const int n0 = blockIdx.x * BN;
    const int m0 = blockIdx.y * BM;
    const int b  = m0 / SEQ;
    const int i0 = m0 % SEQ;

    if (tid < BM)
        prm[tid] = b * SEQ + (use_perm ? perm[i0 + tid] : (i0 + tid));
    __syncthreads();

    // ---- staging: A 2 rows x 2 splits, B 4 rows x 2 splits per thread ----
    const int r0 = tid >> 2;          // 0..63
    const int g  = tid & 3;           // 16B column group
    const int pr0 = prm[r0];
    const int pr1 = prm[r0 + 64];
    const __nv_bfloat16* sAh0 = Ah + (size_t)pr0 * HDIM + g * 8;
    const __nv_bfloat16* sAh1 = Ah + (size_t)pr1 * HDIM + g * 8;
    const __nv_bfloat16* sAl0 = Al + (size_t)pr0 * HDIM + g * 8;
    const __nv_bfloat16* sAl1 = Al + (size_t)pr1 * HDIM + g * 8;
    const __nv_bfloat16* sBh[4];
    const __nv_bfloat16* sBl[4];
    #pragma unroll
    for (int q = 0; q < 4; q++) {
        sBh[q] = Bh + (size_t)(n0 + r0 + q * 64) * HDIM + g * 8;
        sBl[q] = Bl + (size_t)(n0 + r0 + q * 64) * HDIM + g * 8;
    }
    const uint32_t dA0 = (uint32_t)r0 * ROWB + g * 16;
    const uint32_t dA1 = dA0 + 64 * ROWB;

    // ---- ldmatrix per-lane offsets ----
    const uint32_t lrow = (lid & 15);
    const uint32_t lk   = ((lid >> 4) & 1) * 16;
    const uint32_t aOff = (wm * 64 + lrow) * ROWB + lk;
    const uint32_t bOff = (wn * 64 + lrow) * ROWB + lk;

    float acc[4][8][4];
    #pragma unroll
    for (int i = 0; i < 4; i++)
        #pragma unroll
        for (int j = 0; j < 8; j++)
            #pragma unroll
            for (int q = 0; q < 4; q++) acc[i][j][q] = 0.f;

    // ---- prologue: stage chunk 0 into buf 0 ----
    {
        const uint32_t aB = sb + SMP_A;
        const uint32_t bB = sb + SMP_B;
        cp16(aB + dA0,         sAh0); cp16(aB + dA1,         sAh1);
        cp16(aB + 10240 + dA0, sAl0); cp16(aB + 10240 + dA1, sAl1);
        #pragma unroll
        for (int q = 0; q < 4; q++) {
            uint32_t d = (uint32_t)(r0 + q * 64) * ROWB + g * 16;
            cp16(bB + d,         sBh[q]);
            cp16(bB + 20480 + d, sBl[q]);
        }
        cp_commit();
    }

    for (int c = 0; c < NCHUNK; c++) {
        const int buf = c & 1;
        if (c + 1 < NCHUNK) {
            const size_t ko = (size_t)(c + 1) * BK;
            const uint32_t aB = sb + SMP_A + (1 - buf) * A_BUF_STRIDE;
            const uint32_t bB = sb + SMP_B + (1 - buf) * B_BUF_STRIDE;
            cp16(aB + dA0,         sAh0 + ko); cp16(aB + dA1,         sAh1 + ko);
            cp16(aB + 10240 + dA0, sAl0 + ko); cp16(aB + 10240 + dA1, sAl1 + ko);
            #pragma unroll
            for (int q = 0; q < 4; q++) {
                uint32_t d = (uint32_t)(r0 + q * 64) * ROWB + g * 16;
                cp16(bB + d,         sBh[q] + ko);
                cp16(bB + 20480 + d, sBl[q] + ko);
            }
            cp_commit();
            cp_wait1();
        } else {
            cp_wait0();
        }
        __syncthreads();

        const uint32_t aH = sb + SMP_A + buf * A_BUF_STRIDE;
        const uint32_t aL = aH + 10240;
        const uint32_t bH = sb + SMP_B + buf * B_BUF_STRIDE;
        const uint32_t bL = bH + 20480;

        #pragma unroll
        for (int ks = 0; ks < 2; ks++) {
            uint32_t ah[4][4], al[4][4];
            #pragma unroll
            for (int mf = 0; mf < 4; mf++) {
                ldsm4(ah[mf], aH + aOff + mf * (16 * ROWB) + ks * 32);
                ldsm4(al[mf], aL + aOff + mf * (16 * ROWB) + ks * 32);
            }
            #pragma unroll
            for (int p = 0; p < 4; p++) {
                uint32_t tb[4], tl[4];
                ldsm4(tb, bH + bOff + p * (16 * ROWB) + ks * 32);
                ldsm4(tl, bL + bOff + p * (16 * ROWB) + ks * 32);
                #pragma unroll
                for (int mf = 0; mf < 4; mf++) {
                    mma16816(acc[mf][2 * p],     ah[mf], tb[0], tb[2]);
                    mma16816(acc[mf][2 * p],     ah[mf], tl[0], tl[2]);
                    mma16816(acc[mf][2 * p],     al[mf], tb[0], tb[2]);
                    mma16816(acc[mf][2 * p + 1], ah[mf], tb[1], tb[3]);
                    mma16816(acc[mf][2 * p + 1], ah[mf], tl[1], tl[3]);
                    mma16816(acc[mf][2 * p + 1], al[mf], tb[1], tb[3]);
                }
            }
        }
        __syncthreads();
    }

    // ---- epilogue: fragment stores + bias ----
    #pragma unroll
    for (int mf = 0; mf < 4; mf++) {
        const int row = m0 + wm * 64 + mf * 16 + (lid >> 2);
        #pragma unroll
        for (int nf = 0; nf < 8; nf++) {
            const int col = n0 + wn * 64 + nf * 8 + (lid & 3) * 2;
            const float2 bb = *(const float2*)(bias + col);
            float2 v0, v1;
            v0.x = acc[mf][nf][0] + bb.x;  v0.y = acc[mf][nf][1] + bb.y;
            v1.x = acc[mf][nf][2] + bb.x;  v1.y = acc[mf][nf][3] + bb.y;
            *(float2*)(out + (size_t)row * HDIM + col)       = v0;
            *(float2*)(out + (size_t)(row + 8) * HDIM + col) = v1;
        }
    }
}

// ---------------------------------------------------------------------------
// Block attention: 64-token blocks (permuted), headdim 512, fp32.
// Output written directly as split-bf16 (g_xh/g_xl) for the Wo GEMM.
// ---------------------------------------------------------------------------
__global__ void __launch_bounds__(256) attn_kernel(const int* __restrict__ perm)
{
    __shared__ float Qt[64][64];
    __shared__ float Kt[64][64];
    __shared__ float Pt[64][64];

    const int head = blockIdx.x;
    const int b    = blockIdx.y;
    const int tid  = threadIdx.x;
    const int tx   = tid & 15;
    const int ty   = tid >> 4;

    const size_t base = ((size_t)b * SEQ + head * TLEN) * HDIM;
    const float* Qg = g_Q + base;
    const float* Kg = g_K + base;
    const float* Vg = g_V + base;

    float acc[4][4];
    #pragma unroll
    for (int i = 0; i < 4; i++)
        #pragma unroll
        for (int j = 0; j < 4; j++) acc[i][j] = 0.f;

    for (int hc = 0; hc < HDIM; hc += 64) {
        __syncthreads();
        #pragma unroll
        for (int q = 0; q < 4; q++) {
            int idx = tid + q * 256;
            int j   = idx >> 4;
            int k4  = (idx & 15) << 2;
            float4 v = *(const float4*)(Qg + (size_t)j * HDIM + hc + k4);
            Qt[k4 + 0][j] = v.x; Qt[k4 + 1][j] = v.y;
            Qt[k4 + 2][j] = v.z; Qt[k4 + 3][j] = v.w;
            float4 w = *(const float4*)(Kg + (size_t)j * HDIM + hc + k4);
            Kt[k4 + 0][j] = w.x; Kt[k4 + 1][j] = w.y;
            Kt[k4 + 2][j] = w.z; Kt[k4 + 3][j] = w.w;
        }
        __syncthreads();

        #pragma unroll 8
        for (int k = 0; k < 64; k++) {
            float4 a  = *(const float4*)&Qt[k][ty << 2];
            float4 bv = *(const float4*)&Kt[k][tx << 2];
            float ar[4] = {a.x, a.y, a.z, a.w};
            float br[4] = {bv.x, bv.y, bv.z, bv.w};
            #pragma unroll
            for (int i = 0; i < 4; i++)
                #pragma unroll
                for (int j = 0; j < 4; j++)
                    acc[i][j] += ar[i] * br[j];
        }
    }

    const float scale = 0.04419417382415922f;
    #pragma unroll
    for (int i = 0; i < 4; i++) {
        float m = -1e30f;
        #pragma unroll
        for (int j = 0; j < 4; j++) { acc[i][j] *= scale; m = fmaxf(m, acc[i][j]); }
        #pragma unroll
        for (int off = 1; off < 16; off <<= 1)
            m = fmaxf(m, __shfl_xor_sync(0xffffffffu, m, off));
        float p[4], s = 0.f;
        #pragma unroll
        for (int j = 0; j < 4; j++) { p[j] = __expf(acc[i][j] - m); s += p[j]; }
        #pragma unroll
        for (int off = 1; off < 16; off <<= 1)
            s += __shfl_xor_sync(0xffffffffu, s, off);
        float inv = 1.f / s;
        #pragma unroll
        for (int j = 0; j < 4; j++)
            Pt[(tx << 2) + j][(ty << 2) + i] = p[j] * inv;
    }

    int pr[4];
    #pragma unroll
    for (int i = 0; i < 4; i++)
        pr[i] = perm[head * TLEN + (ty << 2) + i];

    __syncthreads();

    for (int hc = 0; hc < HDIM; hc += 64) {
        #pragma unroll
        for (int q = 0; q < 4; q++) {
            int idx = tid + q * 256;
            int j   = idx >> 4;
            int k4  = (idx & 15) << 2;
            *(float4*)&Qt[j][k4] = *(const float4*)(Vg + (size_t)j * HDIM + hc + k4);
        }
        __syncthreads();

        float o[4][4];
        #pragma unroll
        for (int i = 0; i < 4; i++)
            #pragma unroll
            for (int j = 0; j < 4; j++) o[i][j] = 0.f;

        #pragma unroll 8
        for (int k = 0; k < 64; k++) {
            float4 p4 = *(const float4*)&Pt[k][ty << 2];
            float4 v4 = *(const float4*)&Qt[k][tx << 2];
            float pp[4] = {p4.x, p4.y, p4.z, p4.w};
            float vv[4] = {v4.x, v4.y, v4.z, v4.w};
            #pragma unroll
            for (int i = 0; i < 4; i++)
                #pragma unroll
                for (int j = 0; j < 4; j++)
                    o[i][j] += pp[i] * vv[j];
        }

        // write split-bf16 directly (fused hi/lo conversion)
        #pragma unroll
        for (int i = 0; i < 4; i++) {
            size_t adr = ((size_t)b * SEQ + pr[i]) * HDIM + hc + (tx << 2);
            __nv_bfloat162 h2[2], l2[2];
            #pragma unroll
            for (int j = 0; j < 4; j += 2) {
                __nv_bfloat16 h0 = __float2bfloat16(o[i][j]);
                __nv_bfloat16 h1 = __float2bfloat16(o[i][j + 1]);
                __nv_bfloat16 l0 = __float2bfloat16(o[i][j] - __bfloat162float(h0));
                __nv_bfloat16 l1 = __float2bfloat16(o[i][j + 1] - __bfloat162float(h1));
                h2[j >> 1].x = h0; h2[j >> 1].y = h1;
                l2[j >> 1].x = l0; l2[j >> 1].y = l1;
            }
            *(uint2*)(g_xh + adr) = *(uint2*)h2;
            *(uint2*)(g_xl + adr) = *(uint2*)l2;
        }
        __syncthreads();
    }
}

// ---------------------------------------------------------------------------
extern "C" void kernel_launch(void* const* d_in, const int* in_sizes, int n_in,
                              void* d_out, int out_size)
{
    const float* x  = (const float*)d_in[0];
    const float* Wq = (const float*)d_in[1];
    const float* bq = (const float*)d_in[2];
    const float* Wk = (const float*)d_in[3];
    const float* bk = (const float*)d_in[4];
    const float* Wv = (const float*)d_in[5];
    const float* bv = (const float*)d_in[6];
    const float* Wo = (const float*)d_in[7];
    const float* bo = (const float*)d_in[8];
    const int* perm = (const int*)d_in[9];
    float* out = (float*)d_out;

    float *Q, *K, *V;
    __nv_bfloat16 *xh, *xl, *Wh, *Wl;
    cudaGetSymbolAddress((void**)&Q,  g_Q);
    cudaGetSymbolAddress((void**)&K,  g_K);
    cudaGetSymbolAddress((void**)&V,  g_V);
    cudaGetSymbolAddress((void**)&xh, g_xh);
    cudaGetSymbolAddress((void**)&xl, g_xl);
    cudaGetSymbolAddress((void**)&Wh, g_Wh);
    cudaGetSymbolAddress((void**)&Wl, g_Wl);

    cudaFuncSetAttribute(mma_gemm_kernel,
                         cudaFuncAttributeMaxDynamicSharedMemorySize, SMEM_REQ);

    const int WN  = HDIM * HDIM;          // 262144
    const int XN4 = (NROWS * HDIM) / 4;   // 4194304
    const int WN4 = WN / 4;               // 65536

    conv_kernel<<<(XN4 + 255) / 256, 256>>>(x,  xh, xl, XN4);
    conv_kernel<<<(WN4 + 255) / 256, 256>>>(Wq, Wh + 0 * WN, Wl + 0 * WN, WN4);
    conv_kernel<<<(WN4 + 255) / 256, 256>>>(Wk, Wh + 1 * WN, Wl + 1 * WN, WN4);
    conv_kernel<<<(WN4 + 255) / 256, 256>>>(Wv, Wh + 2 * WN, Wl + 2 * WN, WN4);
    conv_kernel<<<(WN4 + 255) / 256, 256>>>(Wo, Wh + 3 * WN, Wl + 3 * WN, WN4);

    dim3 gg(HDIM / BN, NROWS / BM);       // (2, 256)

    mma_gemm_kernel<<<gg, 256, SMEM_REQ>>>(xh, xl, Wh + 0 * WN, Wl + 0 * WN, bq, Q, perm, 1);
    mma_gemm_kernel<<<gg, 256, SMEM_REQ>>>(xh, xl, Wh + 1 * WN, Wl + 1 * WN, bk, K, perm, 1);
    mma_gemm_kernel<<<gg, 256, SMEM_REQ>>>(xh, xl, Wh + 2 * WN, Wl + 2 * WN, bv, V, perm, 1);

    // attn writes g_xh/g_xl (split-bf16) directly — no separate conv pass
    attn_kernel<<<dim3(NHEAD, BATCH), 256>>>(perm);

    mma_gemm_kernel<<<gg, 256, SMEM_REQ>>>(xh, xl, Wh + 3 * WN, Wl + 3 * WN, bo, out, perm, 0);
}

// round 5
// speedup vs baseline: 1.4374x; 1.4374x over previous
#include <cuda_runtime.h>
#include <cuda_fp16.h>
#include <cstdint>

#define BATCH 8
#define SEQ   4096
#define HDIM  512
#define NROWS (BATCH * SEQ)   // 32768
#define NHEAD 64
#define TLEN  64

#define BM 128
#define BN 128
#define BK 32
#define NCHUNK (HDIM / BK)    // 16

#define ROWB 80               // smem row stride bytes (32 fp16 data + pad)

// smem layout (bytes from dynamic base)
#define SMP_PRM   0
#define SMP_A     512                      // [buf] 2 x 10240 (single split)
#define A_BUF_STRIDE 10240
#define SMP_B     (512 + 20480)            // [buf][split] 2 x (2 x 10240)
#define B_BUF_STRIDE 20480
#define SMEM_REQ  (512 + 20480 + 40960)    // 61952

// ---------------- scratch (device globals; allocation-free) ----------------
__device__ float g_Q[NROWS * HDIM];
__device__ float g_K[NROWS * HDIM];
__device__ float g_V[NROWS * HDIM];
__device__ __half g_x16[NROWS * HDIM];          // fp16 activations (x, then attn out)
__device__ __half g_Wh[4 * HDIM * HDIM];        // fp16 weight hi
__device__ __half g_Wl[4 * HDIM * HDIM];        // fp16 weight residual

// ---------------- helpers ----------------
__device__ __forceinline__ uint32_t smem_to_u32(const void* p) {
    uint32_t a;
    asm("{ .reg .u64 t; cvta.to.shared.u64 t, %1; cvt.u32.u64 %0, t; }"
        : "=r"(a) : "l"(p));
    return a;
}
__device__ __forceinline__ void cp16(uint32_t dst, const void* src) {
    asm volatile("cp.async.cg.shared.global [%0], [%1], 16;"
                 :: "r"(dst), "l"(src) : "memory");
}
__device__ __forceinline__ void cp_commit() {
    asm volatile("cp.async.commit_group;" ::: "memory");
}
__device__ __forceinline__ void cp_wait1() {
    asm volatile("cp.async.wait_group 1;" ::: "memory");
}
__device__ __forceinline__ void cp_wait0() {
    asm volatile("cp.async.wait_group 0;" ::: "memory");
}
__device__ __forceinline__ void ldsm4(uint32_t* r, uint32_t addr) {
    asm volatile("ldmatrix.sync.aligned.m8n8.x4.shared.b16 {%0,%1,%2,%3}, [%4];"
                 : "=r"(r[0]), "=r"(r[1]), "=r"(r[2]), "=r"(r[3]) : "r"(addr));
}
__device__ __forceinline__ void mma16816(float* d, const uint32_t* a,
                                         const uint32_t b0, const uint32_t b1) {
    asm volatile(
        "mma.sync.aligned.m16n8k16.row.col.f32.f16.f16.f32 "
        "{%0,%1,%2,%3}, {%4,%5,%6,%7}, {%8,%9}, {%0,%1,%2,%3};"
        : "+f"(d[0]), "+f"(d[1]), "+f"(d[2]), "+f"(d[3])
        : "r"(a[0]), "r"(a[1]), "r"(a[2]), "r"(a[3]), "r"(b0), "r"(b1));
}

// ---------------------------------------------------------------------------
// fp32 -> fp16 (single) conversion, for activations
// ---------------------------------------------------------------------------
__global__ void __launch_bounds__(256) conv_x_kernel(
    const float* __restrict__ src, __half* __restrict__ h, int n4)
{
    int i = blockIdx.x * 256 + threadIdx.x;
    if (i >= n4) return;
    float4 v = ((const float4*)src)[i];
    __half2 a, b;
    a.x = __float2half(v.x); a.y = __float2half(v.y);
    b.x = __float2half(v.z); b.y = __float2half(v.w);
    uint2 o;
    o.x = *(uint32_t*)&a; o.y = *(uint32_t*)&b;
    ((uint2*)h)[i] = o;
}

// ---------------------------------------------------------------------------
// fp32 -> fp16 hi/lo split conversion, for weights
// ---------------------------------------------------------------------------
__global__ void __launch_bounds__(256) conv_w_kernel(
    const float* __restrict__ src, __half* __restrict__ h,
    __half* __restrict__ l, int n4)
{
    int i = blockIdx.x * 256 + threadIdx.x;
    if (i >= n4) return;
    float4 v = ((const float4*)src)[i];
    __half hx = __float2half(v.x);
    __half hy = __float2half(v.y);
    __half hz = __float2half(v.z);
    __half hw = __float2half(v.w);
    __half2 ha, hb, la, lb;
    ha.x = hx; ha.y = hy; hb.x = hz; hb.y = hw;
    la.x = __float2half(v.x - __half2float(hx));
    la.y = __float2half(v.y - __half2float(hy));
    lb.x = __float2half(v.z - __half2float(hz));
    lb.y = __float2half(v.w - __half2float(hw));
    uint2 ho, lo;
    ho.x = *(uint32_t*)&ha; ho.y = *(uint32_t*)&hb;
    lo.x = *(uint32_t*)&la; lo.y = *(uint32_t*)&lb;
    ((uint2*)h)[i] = ho;
    ((uint2*)l)[i] = lo;
}

// ---------------------------------------------------------------------------
// 2-product fp16 GEMM via mma.sync:
//   out[m,n] = sum_k A[rowmap(m),k] * (Wh[n,k] + Wl[n,k]) + bias[n]
// A single fp16, W split fp16. BM=128, BN=128, BK=32, 8 warps (2m x 4n).
// ---------------------------------------------------------------------------
__global__ void __launch_bounds__(256, 2) mma_gemm_kernel(
    const __half* __restrict__ A16,
    const __half* __restrict__ Bh, const __half* __restrict__ Bl,
    const float* __restrict__ bias, float* __restrict__ out,
    const int* __restrict__ perm, int use_perm)
{
    extern __shared__ char smem[];
    const uint32_t sb = smem_to_u32(smem);
    int* prm = (int*)(smem + SMP_PRM);

    const int tid = threadIdx.x;
    const int lid = tid & 31;
    const int wid = tid >> 5;
    const int wm  = wid & 1;    // 0..1  (m)
    const int wn  = wid >> 1;   // 0..3  (n)

    const int n0 = blockIdx.x * BN;
    const int m0 = blockIdx.y * BM;
    const int b  = m0 / SEQ;
    const int i0 = m0 % SEQ;

    if (tid < BM)
        prm[tid] = b * SEQ + (use_perm ? perm[i0 + tid] : (i0 + tid));
    __syncthreads();

    // ---- staging: per thread A 2 rows (1 split), B 2 rows x 2 splits ----
    const int r0 = tid >> 2;          // 0..63
    const int g  = tid & 3;           // 16B column group
    const int pr0 = prm[r0];
    const int pr1 = prm[r0 + 64];
    const __half* sA0 = A16 + (size_t)pr0 * HDIM + g * 8;
    const __half* sA1 = A16 + (size_t)pr1 * HDIM + g * 8;
    const __half* sBh0 = Bh + (size_t)(n0 + r0) * HDIM + g * 8;
    const __half* sBh1 = Bh + (size_t)(n0 + r0 + 64) * HDIM + g * 8;
    const __half* sBl0 = Bl + (size_t)(n0 + r0) * HDIM + g * 8;
    const __half* sBl1 = Bl + (size_t)(n0 + r0 + 64) * HDIM + g * 8;
    const uint32_t d0 = (uint32_t)r0 * ROWB + g * 16;
    const uint32_t d1 = d0 + 64 * ROWB;

    // ---- ldmatrix per-lane offsets ----
    const uint32_t lrow = (lid & 15);
    const uint32_t lk   = ((lid >> 4) & 1) * 16;
    const uint32_t aOff = (wm * 64 + lrow) * ROWB + lk;
    const uint32_t bOff = (wn * 32 + lrow) * ROWB + lk;

    float acc[4][4][4];
    #pragma unroll
    for (int i = 0; i < 4; i++)
        #pragma unroll
        for (int j = 0; j < 4; j++)
            #pragma unroll
            for (int q = 0; q < 4; q++) acc[i][j][q] = 0.f;

    // ---- prologue: stage chunk 0 into buf 0 ----
    {
        const uint32_t aB = sb + SMP_A;
        const uint32_t bB = sb + SMP_B;
        cp16(aB + d0, sA0); cp16(aB + d1, sA1);
        cp16(bB + d0, sBh0); cp16(bB + d1, sBh1);
        cp16(bB + 10240 + d0, sBl0); cp16(bB + 10240 + d1, sBl1);
        cp_commit();
    }

    for (int c = 0; c < NCHUNK; c++) {
        const int buf = c & 1;
        if (c + 1 < NCHUNK) {
            const size_t ko = (size_t)(c + 1) * BK;
            const uint32_t aB = sb + SMP_A + (1 - buf) * A_BUF_STRIDE;
            const uint32_t bB = sb + SMP_B + (1 - buf) * B_BUF_STRIDE;
            cp16(aB + d0, sA0 + ko); cp16(aB + d1, sA1 + ko);
            cp16(bB + d0, sBh0 + ko); cp16(bB + d1, sBh1 + ko);
            cp16(bB + 10240 + d0, sBl0 + ko); cp16(bB + 10240 + d1, sBl1 + ko);
            cp_commit();
            cp_wait1();
        } else {
            cp_wait0();
        }
        __syncthreads();

        const uint32_t aB = sb + SMP_A + buf * A_BUF_STRIDE;
        const uint32_t bH = sb + SMP_B + buf * B_BUF_STRIDE;
        const uint32_t bL = bH + 10240;

        #pragma unroll
        for (int ks = 0; ks < 2; ks++) {
            uint32_t ah[4][4];
            #pragma unroll
            for (int mf = 0; mf < 4; mf++)
                ldsm4(ah[mf], aB + aOff + mf * (16 * ROWB) + ks * 32);
            #pragma unroll
            for (int p = 0; p < 2; p++) {
                uint32_t tb[4], tl[4];
                ldsm4(tb, bH + bOff + p * (16 * ROWB) + ks * 32);
                ldsm4(tl, bL + bOff + p * (16 * ROWB) + ks * 32);
                #pragma unroll
                for (int mf = 0; mf < 4; mf++) {
                    mma16816(acc[mf][2 * p],     ah[mf], tb[0], tb[2]);
                    mma16816(acc[mf][2 * p],     ah[mf], tl[0], tl[2]);
                    mma16816(acc[mf][2 * p + 1], ah[mf], tb[1], tb[3]);
                    mma16816(acc[mf][2 * p + 1], ah[mf], tl[1], tl[3]);
                }
            }
        }
        __syncthreads();
    }

    // ---- epilogue: fragment stores + bias ----
    #pragma unroll
    for (int mf = 0; mf < 4; mf++) {
        const int row = m0 + wm * 64 + mf * 16 + (lid >> 2);
        #pragma unroll
        for (int nf = 0; nf < 4; nf++) {
            const int col = n0 + wn * 32 + nf * 8 + (lid & 3) * 2;
            const float2 bb = *(const float2*)(bias + col);
            float2 v0, v1;
            v0.x = acc[mf][nf][0] + bb.x;  v0.y = acc[mf][nf][1] + bb.y;
            v1.x = acc[mf][nf][2] + bb.x;  v1.y = acc[mf][nf][3] + bb.y;
            *(float2*)(out + (size_t)row * HDIM + col)       = v0;
            *(float2*)(out + (size_t)(row + 8) * HDIM + col) = v1;
        }
    }
}

// ---------------------------------------------------------------------------
// Block attention: 64-token blocks (permuted), headdim 512, fp32 compute.
// Output written directly as fp16 (g_x16) for the Wo GEMM.
// ---------------------------------------------------------------------------
__global__ void __launch_bounds__(256) attn_kernel(const int* __restrict__ perm)
{
    __shared__ float Qt[64][64];
    __shared__ float Kt[64][64];
    __shared__ float Pt[64][64];

    const int head = blockIdx.x;
    const int b    = blockIdx.y;
    const int tid  = threadIdx.x;
    const int tx   = tid & 15;
    const int ty   = tid >> 4;

    const size_t base = ((size_t)b * SEQ + head * TLEN) * HDIM;
    const float* Qg = g_Q + base;
    const float* Kg = g_K + base;
    const float* Vg = g_V + base;

    float acc[4][4];
    #pragma unroll
    for (int i = 0; i < 4; i++)
        #pragma unroll
        for (int j = 0; j < 4; j++) acc[i][j] = 0.f;

    for (int hc = 0; hc < HDIM; hc += 64) {
        __syncthreads();
        #pragma unroll
        for (int q = 0; q < 4; q++) {
            int idx = tid + q * 256;
            int j   = idx >> 4;
            int k4  = (idx & 15) << 2;
            float4 v = *(const float4*)(Qg + (size_t)j * HDIM + hc + k4);
            Qt[k4 + 0][j] = v.x; Qt[k4 + 1][j] = v.y;
            Qt[k4 + 2][j] = v.z; Qt[k4 + 3][j] = v.w;
            float4 w = *(const float4*)(Kg + (size_t)j * HDIM + hc + k4);
            Kt[k4 + 0][j] = w.x; Kt[k4 + 1][j] = w.y;
            Kt[k4 + 2][j] = w.z; Kt[k4 + 3][j] = w.w;
        }
        __syncthreads();

        #pragma unroll 8
        for (int k = 0; k < 64; k++) {
            float4 a  = *(const float4*)&Qt[k][ty << 2];
            float4 bv = *(const float4*)&Kt[k][tx << 2];
            float ar[4] = {a.x, a.y, a.z, a.w};
            float br[4] = {bv.x, bv.y, bv.z, bv.w};
            #pragma unroll
            for (int i = 0; i < 4; i++)
                #pragma unroll
                for (int j = 0; j < 4; j++)
                    acc[i][j] += ar[i] * br[j];
        }
    }

    const float scale = 0.04419417382415922f;
    #pragma unroll
    for (int i = 0; i < 4; i++) {
        float m = -1e30f;
        #pragma unroll
        for (int j = 0; j < 4; j++) { acc[i][j] *= scale; m = fmaxf(m, acc[i][j]); }
        #pragma unroll
        for (int off = 1; off < 16; off <<= 1)
            m = fmaxf(m, __shfl_xor_sync(0xffffffffu, m, off));
        float p[4], s = 0.f;
        #pragma unroll
        for (int j = 0; j < 4; j++) { p[j] = __expf(acc[i][j] - m); s += p[j]; }
        #pragma unroll
        for (int off = 1; off < 16; off <<= 1)
            s += __shfl_xor_sync(0xffffffffu, s, off);
        float inv = 1.f / s;
        #pragma unroll
        for (int j = 0; j < 4; j++)
            Pt[(tx << 2) + j][(ty << 2) + i] = p[j] * inv;
    }

    int pr[4];
    #pragma unroll
    for (int i = 0; i < 4; i++)
        pr[i] = perm[head * TLEN + (ty << 2) + i];

    __syncthreads();

    for (int hc = 0; hc < HDIM; hc += 64) {
        #pragma unroll
        for (int q = 0; q < 4; q++) {
            int idx = tid + q * 256;
            int j   = idx >> 4;
            int k4  = (idx & 15) << 2;
            *(float4*)&Qt[j][k4] = *(const float4*)(Vg + (size_t)j * HDIM + hc + k4);
        }
        __syncthreads();

        float o[4][4];
        #pragma unroll
        for (int i = 0; i < 4; i++)
            #pragma unroll
            for (int j = 0; j < 4; j++) o[i][j] = 0.f;

        #pragma unroll 8
        for (int k = 0; k < 64; k++) {
            float4 p4 = *(const float4*)&Pt[k][ty << 2];
            float4 v4 = *(const float4*)&Qt[k][tx << 2];
            float pp[4] = {p4.x, p4.y, p4.z, p4.w};
            float vv[4] = {v4.x, v4.y, v4.z, v4.w};
            #pragma unroll
            for (int i = 0; i < 4; i++)
                #pragma unroll
                for (int j = 0; j < 4; j++)
                    o[i][j] += pp[i] * vv[j];
        }

        // write fp16 directly (fused conversion for the Wo GEMM)
        #pragma unroll
        for (int i = 0; i < 4; i++) {
            size_t adr = ((size_t)b * SEQ + pr[i]) * HDIM + hc + (tx << 2);
            __half2 h0, h1;
            h0.x = __float2half(o[i][0]); h0.y = __float2half(o[i][1]);
            h1.x = __float2half(o[i][2]); h1.y = __float2half(o[i][3]);
            uint2 pk;
            pk.x = *(uint32_t*)&h0; pk.y = *(uint32_t*)&h1;
            *(uint2*)(g_x16 + adr) = pk;
        }
        __syncthreads();
    }
}

// ---------------------------------------------------------------------------
extern "C" void kernel_launch(void* const* d_in, const int* in_sizes, int n_in,
                              void* d_out, int out_size)
{
    const float* x  = (const float*)d_in[0];
    const float* Wq = (const float*)d_in[1];
    const float* bq = (const float*)d_in[2];
    const float* Wk = (const float*)d_in[3];
    const float* bk = (const float*)d_in[4];
    const float* Wv = (const float*)d_in[5];
    const float* bv = (const float*)d_in[6];
    const float* Wo = (const float*)d_in[7];
    const float* bo = (const float*)d_in[8];
    const int* perm = (const int*)d_in[9];
    float* out = (float*)d_out;

    float *Q, *K, *V;
    __half *x16, *Wh, *Wl;
    cudaGetSymbolAddress((void**)&Q,   g_Q);
    cudaGetSymbolAddress((void**)&K,   g_K);
    cudaGetSymbolAddress((void**)&V,   g_V);
    cudaGetSymbolAddress((void**)&x16, g_x16);
    cudaGetSymbolAddress((void**)&Wh,  g_Wh);
    cudaGetSymbolAddress((void**)&Wl,  g_Wl);

    cudaFuncSetAttribute(mma_gemm_kernel,
                         cudaFuncAttributeMaxDynamicSharedMemorySize, SMEM_REQ);

    const int WN  = HDIM * HDIM;          // 262144
    const int XN4 = (NROWS * HDIM) / 4;   // 4194304
    const int WN4 = WN / 4;               // 65536

    conv_x_kernel<<<(XN4 + 255) / 256, 256>>>(x, x16, XN4);
    conv_w_kernel<<<(WN4 + 255) / 256, 256>>>(Wq, Wh + 0 * WN, Wl + 0 * WN, WN4);
    conv_w_kernel<<<(WN4 + 255) / 256, 256>>>(Wk, Wh + 1 * WN, Wl + 1 * WN, WN4);
    conv_w_kernel<<<(WN4 + 255) / 256, 256>>>(Wv, Wh + 2 * WN, Wl + 2 * WN, WN4);
    conv_w_kernel<<<(WN4 + 255) / 256, 256>>>(Wo, Wh + 3 * WN, Wl + 3 * WN, WN4);

    dim3 gg(HDIM / BN, NROWS / BM);       // (4, 256)

    mma_gemm_kernel<<<gg, 256, SMEM_REQ>>>(x16, Wh + 0 * WN, Wl + 0 * WN, bq, Q, perm, 1);
    mma_gemm_kernel<<<gg, 256, SMEM_REQ>>>(x16, Wh + 1 * WN, Wl + 1 * WN, bk, K, perm, 1);
    mma_gemm_kernel<<<gg, 256, SMEM_REQ>>>(x16, Wh + 2 * WN, Wl + 2 * WN, bv, V, perm, 1);

    // attn writes g_x16 (fp16) directly — no separate conv pass
    attn_kernel<<<dim3(NHEAD, BATCH), 256>>>(perm);

    mma_gemm_kernel<<<gg, 256, SMEM_REQ>>>(x16, Wh + 3 * WN, Wl + 3 * WN, bo, out, perm, 0);
}

// round 6
// speedup vs baseline: 1.6952x; 1.1793x over previous
#include <cuda_runtime.h>
#include <cuda_fp16.h>
#include <cstdint>

#define BATCH 8
#define SEQ   4096
#define HDIM  512
#define NROWS (BATCH * SEQ)   // 32768
#define NHEAD 64
#define TLEN  64

#define BM 128
#define BN 128
#define BK 32
#define NCHUNK (HDIM / BK)    // 16

#define ROWB 80               // GEMM smem row stride bytes (32 fp16 + pad)

// GEMM smem layout
#define SMP_PRM   0
#define SMP_A     512
#define A_BUF_STRIDE 10240
#define SMP_B     (512 + 20480)
#define B_BUF_STRIDE 20480
#define SMEM_REQ  (512 + 20480 + 40960)    // 61952

// attn smem layout: 4 tiles of 64 rows x 272B pitch
#define AT_PITCH  272
#define AT_TILE   (64 * AT_PITCH)          // 17408
#define AT_QH 0
#define AT_QL (AT_TILE)
#define AT_KH (2 * AT_TILE)
#define AT_KL (3 * AT_TILE)
#define AT_VH 0
#define AT_VL (AT_TILE)
#define ATTN_SMEM (4 * AT_TILE)            // 69632

// ---------------- scratch (device globals; allocation-free) ----------------
__device__ __half g_Qh[NROWS * HDIM];
__device__ __half g_Ql[NROWS * HDIM];
__device__ __half g_Kh[NROWS * HDIM];
__device__ __half g_Kl[NROWS * HDIM];
__device__ __half g_Vh[NROWS * HDIM];
__device__ __half g_Vl[NROWS * HDIM];
__device__ __half g_x16[NROWS * HDIM];
__device__ __half g_Wh[4 * HDIM * HDIM];
__device__ __half g_Wl[4 * HDIM * HDIM];

// ---------------- helpers ----------------
__device__ __forceinline__ uint32_t smem_to_u32(const void* p) {
    uint32_t a;
    asm("{ .reg .u64 t; cvta.to.shared.u64 t, %1; cvt.u32.u64 %0, t; }"
        : "=r"(a) : "l"(p));
    return a;
}
__device__ __forceinline__ void cp16(uint32_t dst, const void* src) {
    asm volatile("cp.async.cg.shared.global [%0], [%1], 16;"
                 :: "r"(dst), "l"(src) : "memory");
}
__device__ __forceinline__ void cp_commit() {
    asm volatile("cp.async.commit_group;" ::: "memory");
}
__device__ __forceinline__ void cp_wait1() {
    asm volatile("cp.async.wait_group 1;" ::: "memory");
}
__device__ __forceinline__ void cp_wait0() {
    asm volatile("cp.async.wait_group 0;" ::: "memory");
}
__device__ __forceinline__ void ldsm4(uint32_t* r, uint32_t addr) {
    asm volatile("ldmatrix.sync.aligned.m8n8.x4.shared.b16 {%0,%1,%2,%3}, [%4];"
                 : "=r"(r[0]), "=r"(r[1]), "=r"(r[2]), "=r"(r[3]) : "r"(addr));
}
__device__ __forceinline__ void ldsm4t(uint32_t* r, uint32_t addr) {
    asm volatile("ldmatrix.sync.aligned.m8n8.x4.trans.shared.b16 {%0,%1,%2,%3}, [%4];"
                 : "=r"(r[0]), "=r"(r[1]), "=r"(r[2]), "=r"(r[3]) : "r"(addr));
}
__device__ __forceinline__ void mma16816(float* d, const uint32_t* a,
                                         const uint32_t b0, const uint32_t b1) {
    asm volatile(
        "mma.sync.aligned.m16n8k16.row.col.f32.f16.f16.f32 "
        "{%0,%1,%2,%3}, {%4,%5,%6,%7}, {%8,%9}, {%0,%1,%2,%3};"
        : "+f"(d[0]), "+f"(d[1]), "+f"(d[2]), "+f"(d[3])
        : "r"(a[0]), "r"(a[1]), "r"(a[2]), "r"(a[3]), "r"(b0), "r"(b1));
}
__device__ __forceinline__ uint32_t packh2(float a, float b) {
    __half2 h = __floats2half2_rn(a, b);
    return *(uint32_t*)&h;
}

// ---------------------------------------------------------------------------
// conversions
// ---------------------------------------------------------------------------
__global__ void __launch_bounds__(256) conv_x_kernel(
    const float* __restrict__ src, __half* __restrict__ h, int n4)
{
    int i = blockIdx.x * 256 + threadIdx.x;
    if (i >= n4) return;
    float4 v = ((const float4*)src)[i];
    uint2 o;
    o.x = packh2(v.x, v.y);
    o.y = packh2(v.z, v.w);
    ((uint2*)h)[i] = o;
}

__global__ void __launch_bounds__(256) conv_w_kernel(
    const float* __restrict__ src, __half* __restrict__ h,
    __half* __restrict__ l, int n4)
{
    int i = blockIdx.x * 256 + threadIdx.x;
    if (i >= n4) return;
    float4 v = ((const float4*)src)[i];
    float f[4] = {v.x, v.y, v.z, v.w};
    __half hh[4], ll[4];
    #pragma unroll
    for (int q = 0; q < 4; q++) {
        hh[q] = __float2half(f[q]);
        ll[q] = __float2half(f[q] - __half2float(hh[q]));
    }
    ((uint2*)h)[i] = *(uint2*)hh;
    ((uint2*)l)[i] = *(uint2*)ll;
}

// ---------------------------------------------------------------------------
// 2-product fp16 GEMM: out[m,n] = sum_k A[rowmap(m),k]*(Wh+Wl)[n,k] + bias[n]
// Epilogue: fp32 out (outf) OR split-fp16 out (outh/outl).
// ---------------------------------------------------------------------------
__global__ void __launch_bounds__(256, 2) mma_gemm_kernel(
    const __half* __restrict__ A16,
    const __half* __restrict__ Bh, const __half* __restrict__ Bl,
    const float* __restrict__ bias, float* __restrict__ outf,
    __half* __restrict__ outh, __half* __restrict__ outl,
    const int* __restrict__ perm, int use_perm)
{
    extern __shared__ char smem[];
    const uint32_t sb = smem_to_u32(smem);
    int* prm = (int*)(smem + SMP_PRM);

    const int tid = threadIdx.x;
    const int lid = tid & 31;
    const int wid = tid >> 5;
    const int wm  = wid & 1;
    const int wn  = wid >> 1;

    const int n0 = blockIdx.x * BN;
    const int m0 = blockIdx.y * BM;
    const int b  = m0 / SEQ;
    const int i0 = m0 % SEQ;

    if (tid < BM)
        prm[tid] = b * SEQ + (use_perm ? perm[i0 + tid] : (i0 + tid));
    __syncthreads();

    const int r0 = tid >> 2;
    const int g  = tid & 3;
    const int pr0 = prm[r0];
    const int pr1 = prm[r0 + 64];
    const __half* sA0 = A16 + (size_t)pr0 * HDIM + g * 8;
    const __half* sA1 = A16 + (size_t)pr1 * HDIM + g * 8;
    const __half* sBh0 = Bh + (size_t)(n0 + r0) * HDIM + g * 8;
    const __half* sBh1 = Bh + (size_t)(n0 + r0 + 64) * HDIM + g * 8;
    const __half* sBl0 = Bl + (size_t)(n0 + r0) * HDIM + g * 8;
    const __half* sBl1 = Bl + (size_t)(n0 + r0 + 64) * HDIM + g * 8;
    const uint32_t d0 = (uint32_t)r0 * ROWB + g * 16;
    const uint32_t d1 = d0 + 64 * ROWB;

    const uint32_t lrow = (lid & 15);
    const uint32_t lk   = ((lid >> 4) & 1) * 16;
    const uint32_t aOff = (wm * 64 + lrow) * ROWB + lk;
    const uint32_t bOff = (wn * 32 + lrow) * ROWB + lk;

    float acc[4][4][4];
    #pragma unroll
    for (int i = 0; i < 4; i++)
        #pragma unroll
        for (int j = 0; j < 4; j++)
            #pragma unroll
            for (int q = 0; q < 4; q++) acc[i][j][q] = 0.f;

    {
        const uint32_t aB = sb + SMP_A;
        const uint32_t bB = sb + SMP_B;
        cp16(aB + d0, sA0); cp16(aB + d1, sA1);
        cp16(bB + d0, sBh0); cp16(bB + d1, sBh1);
        cp16(bB + 10240 + d0, sBl0); cp16(bB + 10240 + d1, sBl1);
        cp_commit();
    }

    for (int c = 0; c < NCHUNK; c++) {
        const int buf = c & 1;
        if (c + 1 < NCHUNK) {
            const size_t ko = (size_t)(c + 1) * BK;
            const uint32_t aB = sb + SMP_A + (1 - buf) * A_BUF_STRIDE;
            const uint32_t bB = sb + SMP_B + (1 - buf) * B_BUF_STRIDE;
            cp16(aB + d0, sA0 + ko); cp16(aB + d1, sA1 + ko);
            cp16(bB + d0, sBh0 + ko); cp16(bB + d1, sBh1 + ko);
            cp16(bB + 10240 + d0, sBl0 + ko); cp16(bB + 10240 + d1, sBl1 + ko);
            cp_commit();
            cp_wait1();
        } else {
            cp_wait0();
        }
        __syncthreads();

        const uint32_t aB = sb + SMP_A + buf * A_BUF_STRIDE;
        const uint32_t bH = sb + SMP_B + buf * B_BUF_STRIDE;
        const uint32_t bL = bH + 10240;

        #pragma unroll
        for (int ks = 0; ks < 2; ks++) {
            uint32_t ah[4][4];
            #pragma unroll
            for (int mf = 0; mf < 4; mf++)
                ldsm4(ah[mf], aB + aOff + mf * (16 * ROWB) + ks * 32);
            #pragma unroll
            for (int p = 0; p < 2; p++) {
                uint32_t tb[4], tl[4];
                ldsm4(tb, bH + bOff + p * (16 * ROWB) + ks * 32);
                ldsm4(tl, bL + bOff + p * (16 * ROWB) + ks * 32);
                #pragma unroll
                for (int mf = 0; mf < 4; mf++) {
                    mma16816(acc[mf][2 * p],     ah[mf], tb[0], tb[2]);
                    mma16816(acc[mf][2 * p],     ah[mf], tl[0], tl[2]);
                    mma16816(acc[mf][2 * p + 1], ah[mf], tb[1], tb[3]);
                    mma16816(acc[mf][2 * p + 1], ah[mf], tl[1], tl[3]);
                }
            }
        }
        __syncthreads();
    }

    // ---- epilogue ----
    #pragma unroll
    for (int mf = 0; mf < 4; mf++) {
        const int row = m0 + wm * 64 + mf * 16 + (lid >> 2);
        #pragma unroll
        for (int nf = 0; nf < 4; nf++) {
            const int col = n0 + wn * 32 + nf * 8 + (lid & 3) * 2;
            const float2 bb = *(const float2*)(bias + col);
            float v00 = acc[mf][nf][0] + bb.x, v01 = acc[mf][nf][1] + bb.y;
            float v10 = acc[mf][nf][2] + bb.x, v11 = acc[mf][nf][3] + bb.y;
            if (outf) {
                *(float2*)(outf + (size_t)row * HDIM + col) = make_float2(v00, v01);
                *(float2*)(outf + (size_t)(row + 8) * HDIM + col) = make_float2(v10, v11);
            } else {
                __half h00 = __float2half(v00), h01 = __float2half(v01);
                __half h10 = __float2half(v10), h11 = __float2half(v11);
                __half2 hp0, hp1, lp0, lp1;
                hp0.x = h00; hp0.y = h01;
                hp1.x = h10; hp1.y = h11;
                lp0.x = __float2half(v00 - __half2float(h00));
                lp0.y = __float2half(v01 - __half2float(h01));
                lp1.x = __float2half(v10 - __half2float(h10));
                lp1.y = __float2half(v11 - __half2float(h11));
                *(uint32_t*)(outh + (size_t)row * HDIM + col)       = *(uint32_t*)&hp0;
                *(uint32_t*)(outh + (size_t)(row + 8) * HDIM + col) = *(uint32_t*)&hp1;
                *(uint32_t*)(outl + (size_t)row * HDIM + col)       = *(uint32_t*)&lp0;
                *(uint32_t*)(outl + (size_t)(row + 8) * HDIM + col) = *(uint32_t*)&lp1;
            }
        }
    }
}

// ---------------------------------------------------------------------------
// Tensorized block attention. 1 block per (head,batch), 128 threads / 4 warps.
// scores = 3-product split fp16 MMA; softmax fp32 in registers;
// AV = 2-product (P_fp16 * (Vh+Vl)); output scattered via perm as fp16.
// ---------------------------------------------------------------------------
__global__ void __launch_bounds__(128) attn_kernel(const int* __restrict__ perm)
{
    extern __shared__ char smem[];
    const uint32_t sb = smem_to_u32(smem);

    const int head = blockIdx.x;
    const int b    = blockIdx.y;
    const int tid  = threadIdx.x;
    const int lid  = tid & 31;
    const int wm   = tid >> 5;            // warp 0..3, rows wm*16..+15

    const size_t tokbase = (size_t)b * SEQ + head * TLEN;

    const uint32_t lr = lid & 15;
    const uint32_t lkb = ((lid >> 4) & 1) * 16;   // 16B k-half for ldsm

    // ---- Phase 1: scores (64x64) ----
    float sc[8][4];
    #pragma unroll
    for (int i = 0; i < 8; i++)
        #pragma unroll
        for (int q = 0; q < 4; q++) sc[i][q] = 0.f;

    for (int hcb = 0; hcb < 4; hcb++) {
        const int hc = hcb * 128;
        __syncthreads();
        // stage Qh/Ql/Kh/Kl tiles: 64 rows x 128 halfs each
        {
            const __half* srcs[4] = {
                g_Qh + tokbase * HDIM, g_Ql + tokbase * HDIM,
                g_Kh + tokbase * HDIM, g_Kl + tokbase * HDIM };
            const uint32_t dsts[4] = {sb + AT_QH, sb + AT_QL, sb + AT_KH, sb + AT_KL};
            #pragma unroll
            for (int t = 0; t < 4; t++) {
                #pragma unroll
                for (int i = 0; i < 8; i++) {
                    int idx = tid + i * 128;          // 0..1023
                    int r = idx >> 4, cg = idx & 15;
                    cp16(dsts[t] + r * AT_PITCH + cg * 16,
                         srcs[t] + (size_t)r * HDIM + hc + cg * 8);
                }
            }
            cp_commit(); cp_wait0();
        }
        __syncthreads();

        #pragma unroll
        for (int ks = 0; ks < 8; ks++) {
            uint32_t qh[4], ql[4];
            ldsm4(qh, sb + AT_QH + (wm * 16 + lr) * AT_PITCH + ks * 32 + lkb);
            ldsm4(ql, sb + AT_QL + (wm * 16 + lr) * AT_PITCH + ks * 32 + lkb);
            #pragma unroll
            for (int p = 0; p < 4; p++) {
                uint32_t kh[4], kl[4];
                ldsm4(kh, sb + AT_KH + (p * 16 + lr) * AT_PITCH + ks * 32 + lkb);
                ldsm4(kl, sb + AT_KL + (p * 16 + lr) * AT_PITCH + ks * 32 + lkb);
                mma16816(sc[2 * p],     qh, kh[0], kh[2]);
                mma16816(sc[2 * p],     qh, kl[0], kl[2]);
                mma16816(sc[2 * p],     ql, kh[0], kh[2]);
                mma16816(sc[2 * p + 1], qh, kh[1], kh[3]);
                mma16816(sc[2 * p + 1], qh, kl[1], kl[3]);
                mma16816(sc[2 * p + 1], ql, kh[1], kh[3]);
            }
        }
    }

    // ---- Softmax (rows r = wm*16 + lid>>2 and +8) ----
    const float scale = 0.04419417382415922f;   // 1/sqrt(512)
    float mx0 = -1e30f, mx1 = -1e30f;
    #pragma unroll
    for (int nf = 0; nf < 8; nf++) {
        #pragma unroll
        for (int q = 0; q < 4; q++) sc[nf][q] *= scale;
        mx0 = fmaxf(mx0, fmaxf(sc[nf][0], sc[nf][1]));
        mx1 = fmaxf(mx1, fmaxf(sc[nf][2], sc[nf][3]));
    }
    mx0 = fmaxf(mx0, __shfl_xor_sync(0xffffffffu, mx0, 1));
    mx0 = fmaxf(mx0, __shfl_xor_sync(0xffffffffu, mx0, 2));
    mx1 = fmaxf(mx1, __shfl_xor_sync(0xffffffffu, mx1, 1));
    mx1 = fmaxf(mx1, __shfl_xor_sync(0xffffffffu, mx1, 2));

    float s0 = 0.f, s1 = 0.f;
    #pragma unroll
    for (int nf = 0; nf < 8; nf++) {
        sc[nf][0] = __expf(sc[nf][0] - mx0); s0 += sc[nf][0];
        sc[nf][1] = __expf(sc[nf][1] - mx0); s0 += sc[nf][1];
        sc[nf][2] = __expf(sc[nf][2] - mx1); s1 += sc[nf][2];
        sc[nf][3] = __expf(sc[nf][3] - mx1); s1 += sc[nf][3];
    }
    s0 += __shfl_xor_sync(0xffffffffu, s0, 1);
    s0 += __shfl_xor_sync(0xffffffffu, s0, 2);
    s1 += __shfl_xor_sync(0xffffffffu, s1, 1);
    s1 += __shfl_xor_sync(0xffffffffu, s1, 2);
    const float inv0 = 1.f / s0, inv1 = 1.f / s1;

    // P fragments as fp16 A-operands for AV (kstep j covers tokens 16j..16j+15)
    uint32_t pa[4][4];
    #pragma unroll
    for (int j = 0; j < 4; j++) {
        pa[j][0] = packh2(sc[2 * j][0] * inv0,     sc[2 * j][1] * inv0);
        pa[j][1] = packh2(sc[2 * j][2] * inv1,     sc[2 * j][3] * inv1);
        pa[j][2] = packh2(sc[2 * j + 1][0] * inv0, sc[2 * j + 1][1] * inv0);
        pa[j][3] = packh2(sc[2 * j + 1][2] * inv1, sc[2 * j + 1][3] * inv1);
    }

    const int prow0 = perm[head * TLEN + wm * 16 + (lid >> 2)];
    const int prow8 = perm[head * TLEN + wm * 16 + (lid >> 2) + 8];
    const size_t obase0 = ((size_t)b * SEQ + prow0) * HDIM;
    const size_t obase8 = ((size_t)b * SEQ + prow8) * HDIM;

    // ---- Phase 2: O = P V, 4 chunks of 128 output cols ----
    for (int hcb = 0; hcb < 4; hcb++) {
        const int hc = hcb * 128;
        __syncthreads();
        {
            const __half* srcs[2] = {g_Vh + tokbase * HDIM, g_Vl + tokbase * HDIM};
            const uint32_t dsts[2] = {sb + AT_VH, sb + AT_VL};
            #pragma unroll
            for (int t = 0; t < 2; t++) {
                #pragma unroll
                for (int i = 0; i < 8; i++) {
                    int idx = tid + i * 128;
                    int r = idx >> 4, cg = idx & 15;
                    cp16(dsts[t] + r * AT_PITCH + cg * 16,
                         srcs[t] + (size_t)r * HDIM + hc + cg * 8);
                }
            }
            cp_commit(); cp_wait0();
        }
        __syncthreads();

        float o[16][4];
        #pragma unroll
        for (int i = 0; i < 16; i++)
            #pragma unroll
            for (int q = 0; q < 4; q++) o[i][q] = 0.f;

        #pragma unroll
        for (int j = 0; j < 4; j++) {        // k-steps (tokens 16j..16j+15)
            #pragma unroll
            for (int nf2 = 0; nf2 < 8; nf2++) {   // 16-col groups
                const uint32_t coff = (nf2 * 16 + ((lid >> 4) & 1) * 8) * 2;
                uint32_t vh[4], vl[4];
                ldsm4t(vh, sb + AT_VH + (j * 16 + lr) * AT_PITCH + coff);
                ldsm4t(vl, sb + AT_VL + (j * 16 + lr) * AT_PITCH + coff);
                mma16816(o[2 * nf2],     pa[j], vh[0], vh[1]);
                mma16816(o[2 * nf2],     pa[j], vl[0], vl[1]);
                mma16816(o[2 * nf2 + 1], pa[j], vh[2], vh[3]);
                mma16816(o[2 * nf2 + 1], pa[j], vl[2], vl[3]);
            }
        }

        // scatter-write fp16
        #pragma unroll
        for (int nf = 0; nf < 16; nf++) {
            const int col = hc + nf * 8 + (lid & 3) * 2;
            *(uint32_t*)(g_x16 + obase0 + col) = packh2(o[nf][0], o[nf][1]);
            *(uint32_t*)(g_x16 + obase8 + col) = packh2(o[nf][2], o[nf][3]);
        }
    }
}

// ---------------------------------------------------------------------------
extern "C" void kernel_launch(void* const* d_in, const int* in_sizes, int n_in,
                              void* d_out, int out_size)
{
    const float* x  = (const float*)d_in[0];
    const float* Wq = (const float*)d_in[1];
    const float* bq = (const float*)d_in[2];
    const float* Wk = (const float*)d_in[3];
    const float* bk = (const float*)d_in[4];
    const float* Wv = (const float*)d_in[5];
    const float* bv = (const float*)d_in[6];
    const float* Wo = (const float*)d_in[7];
    const float* bo = (const float*)d_in[8];
    const int* perm = (const int*)d_in[9];
    float* out = (float*)d_out;

    __half *x16, *Wh, *Wl, *Qh, *Ql, *Kh, *Kl, *Vh, *Vl;
    cudaGetSymbolAddress((void**)&x16, g_x16);
    cudaGetSymbolAddress((void**)&Wh,  g_Wh);
    cudaGetSymbolAddress((void**)&Wl,  g_Wl);
    cudaGetSymbolAddress((void**)&Qh,  g_Qh);
    cudaGetSymbolAddress((void**)&Ql,  g_Ql);
    cudaGetSymbolAddress((void**)&Kh,  g_Kh);
    cudaGetSymbolAddress((void**)&Kl,  g_Kl);
    cudaGetSymbolAddress((void**)&Vh,  g_Vh);
    cudaGetSymbolAddress((void**)&Vl,  g_Vl);

    cudaFuncSetAttribute(mma_gemm_kernel,
                         cudaFuncAttributeMaxDynamicSharedMemorySize, SMEM_REQ);
    cudaFuncSetAttribute(attn_kernel,
                         cudaFuncAttributeMaxDynamicSharedMemorySize, ATTN_SMEM);

    const int WN  = HDIM * HDIM;
    const int XN4 = (NROWS * HDIM) / 4;
    const int WN4 = WN / 4;

    conv_x_kernel<<<(XN4 + 255) / 256, 256>>>(x, x16, XN4);
    conv_w_kernel<<<(WN4 + 255) / 256, 256>>>(Wq, Wh + 0 * WN, Wl + 0 * WN, WN4);
    conv_w_kernel<<<(WN4 + 255) / 256, 256>>>(Wk, Wh + 1 * WN, Wl + 1 * WN, WN4);
    conv_w_kernel<<<(WN4 + 255) / 256, 256>>>(Wv, Wh + 2 * WN, Wl + 2 * WN, WN4);
    conv_w_kernel<<<(WN4 + 255) / 256, 256>>>(Wo, Wh + 3 * WN, Wl + 3 * WN, WN4);

    dim3 gg(HDIM / BN, NROWS / BM);       // (4, 256)

    // QKV projections -> split fp16 outputs (permuted row order)
    mma_gemm_kernel<<<gg, 256, SMEM_REQ>>>(x16, Wh + 0 * WN, Wl + 0 * WN, bq,
                                           nullptr, Qh, Ql, perm, 1);
    mma_gemm_kernel<<<gg, 256, SMEM_REQ>>>(x16, Wh + 1 * WN, Wl + 1 * WN, bk,
                                           nullptr, Kh, Kl, perm, 1);
    mma_gemm_kernel<<<gg, 256, SMEM_REQ>>>(x16, Wh + 2 * WN, Wl + 2 * WN, bv,
                                           nullptr, Vh, Vl, perm, 1);

    // tensorized attention -> g_x16 (fp16, un-permuted)
    attn_kernel<<<dim3(NHEAD, BATCH), 128, ATTN_SMEM>>>(perm);

    // output projection -> fp32 out
    mma_gemm_kernel<<<gg, 256, SMEM_REQ>>>(x16, Wh + 3 * WN, Wl + 3 * WN, bo,
                                           out, nullptr, nullptr, perm, 0);
}

// round 7
// speedup vs baseline: 2.5583x; 1.5092x over previous
#include <cuda_runtime.h>
#include <cuda_fp16.h>
#include <cstdint>

#define BATCH 8
#define SEQ   4096
#define HDIM  512
#define NROWS (BATCH * SEQ)   // 32768
#define NHEAD 64
#define TLEN  64

#define BM 128
#define BN 128
#define BK 32
#define NCHUNK (HDIM / BK)    // 16

#define ROWB 80               // GEMM smem row stride bytes (32 fp16 + pad)

// GEMM smem layout (single-split A and B, double buffered)
#define SMP_PRM   0
#define SMP_A     512
#define A_BUF_STRIDE 10240
#define SMP_B     (512 + 20480)
#define B_BUF_STRIDE 10240
#define SMEM_REQ  (512 + 20480 + 20480)    // 41472

// attn smem layout: 4 tiles of 64 rows x 272B pitch
#define AT_PITCH  272
#define AT_TILE   (64 * AT_PITCH)          // 17408
#define AT_QH 0
#define AT_QL (AT_TILE)
#define AT_KH (2 * AT_TILE)
#define AT_KL (3 * AT_TILE)
#define AT_VH 0
#define AT_VL (AT_TILE)
#define ATTN_SMEM (4 * AT_TILE)            // 69632

// ---------------- scratch (device globals; allocation-free) ----------------
__device__ __half g_Qh[NROWS * HDIM];
__device__ __half g_Ql[NROWS * HDIM];
__device__ __half g_Kh[NROWS * HDIM];
__device__ __half g_Kl[NROWS * HDIM];
__device__ __half g_Vh[NROWS * HDIM];
__device__ __half g_Vl[NROWS * HDIM];
__device__ __half g_x16[NROWS * HDIM];
__device__ __half g_Wh[4 * HDIM * HDIM];

// ---------------- helpers ----------------
__device__ __forceinline__ uint32_t smem_to_u32(const void* p) {
    uint32_t a;
    asm("{ .reg .u64 t; cvta.to.shared.u64 t, %1; cvt.u32.u64 %0, t; }"
        : "=r"(a) : "l"(p));
    return a;
}
__device__ __forceinline__ void cp16(uint32_t dst, const void* src) {
    asm volatile("cp.async.cg.shared.global [%0], [%1], 16;"
                 :: "r"(dst), "l"(src) : "memory");
}
__device__ __forceinline__ void cp_commit() {
    asm volatile("cp.async.commit_group;" ::: "memory");
}
__device__ __forceinline__ void cp_wait1() {
    asm volatile("cp.async.wait_group 1;" ::: "memory");
}
__device__ __forceinline__ void cp_wait0() {
    asm volatile("cp.async.wait_group 0;" ::: "memory");
}
__device__ __forceinline__ void ldsm4(uint32_t* r, uint32_t addr) {
    asm volatile("ldmatrix.sync.aligned.m8n8.x4.shared.b16 {%0,%1,%2,%3}, [%4];"
                 : "=r"(r[0]), "=r"(r[1]), "=r"(r[2]), "=r"(r[3]) : "r"(addr));
}
__device__ __forceinline__ void ldsm4t(uint32_t* r, uint32_t addr) {
    asm volatile("ldmatrix.sync.aligned.m8n8.x4.trans.shared.b16 {%0,%1,%2,%3}, [%4];"
                 : "=r"(r[0]), "=r"(r[1]), "=r"(r[2]), "=r"(r[3]) : "r"(addr));
}
__device__ __forceinline__ void mma16816(float* d, const uint32_t* a,
                                         const uint32_t b0, const uint32_t b1) {
    asm volatile(
        "mma.sync.aligned.m16n8k16.row.col.f32.f16.f16.f32 "
        "{%0,%1,%2,%3}, {%4,%5,%6,%7}, {%8,%9}, {%0,%1,%2,%3};"
        : "+f"(d[0]), "+f"(d[1]), "+f"(d[2]), "+f"(d[3])
        : "r"(a[0]), "r"(a[1]), "r"(a[2]), "r"(a[3]), "r"(b0), "r"(b1));
}
__device__ __forceinline__ uint32_t packh2(float a, float b) {
    __half2 h = __floats2half2_rn(a, b);
    return *(uint32_t*)&h;
}

// ---------------------------------------------------------------------------
// conversions (fp32 -> single fp16)
// ---------------------------------------------------------------------------
__global__ void __launch_bounds__(256) conv_x_kernel(
    const float* __restrict__ src, __half* __restrict__ h, int n4)
{
    int i = blockIdx.x * 256 + threadIdx.x;
    if (i >= n4) return;
    float4 v = ((const float4*)src)[i];
    uint2 o;
    o.x = packh2(v.x, v.y);
    o.y = packh2(v.z, v.w);
    ((uint2*)h)[i] = o;
}

// ---------------------------------------------------------------------------
// single-product fp16 GEMM: out[m,n] = sum_k A[rowmap(m),k]*W[n,k] + bias[n]
// Epilogue: fp32 out (outf) OR split-fp16 out (outh/outl).
// ---------------------------------------------------------------------------
__global__ void __launch_bounds__(256, 2) mma_gemm_kernel(
    const __half* __restrict__ A16, const __half* __restrict__ Bh,
    const float* __restrict__ bias, float* __restrict__ outf,
    __half* __restrict__ outh, __half* __restrict__ outl,
    const int* __restrict__ perm, int use_perm)
{
    extern __shared__ char smem[];
    const uint32_t sb = smem_to_u32(smem);
    int* prm = (int*)(smem + SMP_PRM);

    const int tid = threadIdx.x;
    const int lid = tid & 31;
    const int wid = tid >> 5;
    const int wm  = wid & 1;
    const int wn  = wid >> 1;

    const int n0 = blockIdx.x * BN;
    const int m0 = blockIdx.y * BM;
    const int b  = m0 / SEQ;
    const int i0 = m0 % SEQ;

    if (tid < BM)
        prm[tid] = b * SEQ + (use_perm ? perm[i0 + tid] : (i0 + tid));
    __syncthreads();

    const int r0 = tid >> 2;
    const int g  = tid & 3;
    const int pr0 = prm[r0];
    const int pr1 = prm[r0 + 64];
    const __half* sA0 = A16 + (size_t)pr0 * HDIM + g * 8;
    const __half* sA1 = A16 + (size_t)pr1 * HDIM + g * 8;
    const __half* sB0 = Bh + (size_t)(n0 + r0) * HDIM + g * 8;
    const __half* sB1 = Bh + (size_t)(n0 + r0 + 64) * HDIM + g * 8;
    const uint32_t d0 = (uint32_t)r0 * ROWB + g * 16;
    const uint32_t d1 = d0 + 64 * ROWB;

    const uint32_t lrow = (lid & 15);
    const uint32_t lk   = ((lid >> 4) & 1) * 16;
    const uint32_t aOff = (wm * 64 + lrow) * ROWB + lk;
    const uint32_t bOff = (wn * 32 + lrow) * ROWB + lk;

    float acc[4][4][4];
    #pragma unroll
    for (int i = 0; i < 4; i++)
        #pragma unroll
        for (int j = 0; j < 4; j++)
            #pragma unroll
            for (int q = 0; q < 4; q++) acc[i][j][q] = 0.f;

    {
        const uint32_t aB = sb + SMP_A;
        const uint32_t bB = sb + SMP_B;
        cp16(aB + d0, sA0); cp16(aB + d1, sA1);
        cp16(bB + d0, sB0); cp16(bB + d1, sB1);
        cp_commit();
    }

    for (int c = 0; c < NCHUNK; c++) {
        const int buf = c & 1;
        if (c + 1 < NCHUNK) {
            const size_t ko = (size_t)(c + 1) * BK;
            const uint32_t aB = sb + SMP_A + (1 - buf) * A_BUF_STRIDE;
            const uint32_t bB = sb + SMP_B + (1 - buf) * B_BUF_STRIDE;
            cp16(aB + d0, sA0 + ko); cp16(aB + d1, sA1 + ko);
            cp16(bB + d0, sB0 + ko); cp16(bB + d1, sB1 + ko);
            cp_commit();
            cp_wait1();
        } else {
            cp_wait0();
        }
        __syncthreads();

        const uint32_t aB = sb + SMP_A + buf * A_BUF_STRIDE;
        const uint32_t bB = sb + SMP_B + buf * B_BUF_STRIDE;

        #pragma unroll
        for (int ks = 0; ks < 2; ks++) {
            uint32_t ah[4][4];
            #pragma unroll
            for (int mf = 0; mf < 4; mf++)
                ldsm4(ah[mf], aB + aOff + mf * (16 * ROWB) + ks * 32);
            #pragma unroll
            for (int p = 0; p < 2; p++) {
                uint32_t tb[4];
                ldsm4(tb, bB + bOff + p * (16 * ROWB) + ks * 32);
                #pragma unroll
                for (int mf = 0; mf < 4; mf++) {
                    mma16816(acc[mf][2 * p],     ah[mf], tb[0], tb[2]);
                    mma16816(acc[mf][2 * p + 1], ah[mf], tb[1], tb[3]);
                }
            }
        }
        __syncthreads();
    }

    // ---- epilogue ----
    #pragma unroll
    for (int mf = 0; mf < 4; mf++) {
        const int row = m0 + wm * 64 + mf * 16 + (lid >> 2);
        #pragma unroll
        for (int nf = 0; nf < 4; nf++) {
            const int col = n0 + wn * 32 + nf * 8 + (lid & 3) * 2;
            const float2 bb = *(const float2*)(bias + col);
            float v00 = acc[mf][nf][0] + bb.x, v01 = acc[mf][nf][1] + bb.y;
            float v10 = acc[mf][nf][2] + bb.x, v11 = acc[mf][nf][3] + bb.y;
            if (outf) {
                *(float2*)(outf + (size_t)row * HDIM + col) = make_float2(v00, v01);
                *(float2*)(outf + (size_t)(row + 8) * HDIM + col) = make_float2(v10, v11);
            } else {
                __half h00 = __float2half(v00), h01 = __float2half(v01);
                __half h10 = __float2half(v10), h11 = __float2half(v11);
                __half2 hp0, hp1, lp0, lp1;
                hp0.x = h00; hp0.y = h01;
                hp1.x = h10; hp1.y = h11;
                lp0.x = __float2half(v00 - __half2float(h00));
                lp0.y = __float2half(v01 - __half2float(h01));
                lp1.x = __float2half(v10 - __half2float(h10));
                lp1.y = __float2half(v11 - __half2float(h11));
                *(uint32_t*)(outh + (size_t)row * HDIM + col)       = *(uint32_t*)&hp0;
                *(uint32_t*)(outh + (size_t)(row + 8) * HDIM + col) = *(uint32_t*)&hp1;
                *(uint32_t*)(outl + (size_t)row * HDIM + col)       = *(uint32_t*)&lp0;
                *(uint32_t*)(outl + (size_t)(row + 8) * HDIM + col) = *(uint32_t*)&lp1;
            }
        }
    }
}

// ---------------------------------------------------------------------------
// Tensorized block attention (unchanged from R6 — split paths preserved).
// ---------------------------------------------------------------------------
__global__ void __launch_bounds__(128) attn_kernel(const int* __restrict__ perm)
{
    extern __shared__ char smem[];
    const uint32_t sb = smem_to_u32(smem);

    const int head = blockIdx.x;
    const int b    = blockIdx.y;
    const int tid  = threadIdx.x;
    const int lid  = tid & 31;
    const int wm   = tid >> 5;

    const size_t tokbase = (size_t)b * SEQ + head * TLEN;

    const uint32_t lr = lid & 15;
    const uint32_t lkb = ((lid >> 4) & 1) * 16;

    float sc[8][4];
    #pragma unroll
    for (int i = 0; i < 8; i++)
        #pragma unroll
        for (int q = 0; q < 4; q++) sc[i][q] = 0.f;

    for (int hcb = 0; hcb < 4; hcb++) {
        const int hc = hcb * 128;
        __syncthreads();
        {
            const __half* srcs[4] = {
                g_Qh + tokbase * HDIM, g_Ql + tokbase * HDIM,
                g_Kh + tokbase * HDIM, g_Kl + tokbase * HDIM };
            const uint32_t dsts[4] = {sb + AT_QH, sb + AT_QL, sb + AT_KH, sb + AT_KL};
            #pragma unroll
            for (int t = 0; t < 4; t++) {
                #pragma unroll
                for (int i = 0; i < 8; i++) {
                    int idx = tid + i * 128;
                    int r = idx >> 4, cg = idx & 15;
                    cp16(dsts[t] + r * AT_PITCH + cg * 16,
                         srcs[t] + (size_t)r * HDIM + hc + cg * 8);
                }
            }
            cp_commit(); cp_wait0();
        }
        __syncthreads();

        #pragma unroll
        for (int ks = 0; ks < 8; ks++) {
            uint32_t qh[4], ql[4];
            ldsm4(qh, sb + AT_QH + (wm * 16 + lr) * AT_PITCH + ks * 32 + lkb);
            ldsm4(ql, sb + AT_QL + (wm * 16 + lr) * AT_PITCH + ks * 32 + lkb);
            #pragma unroll
            for (int p = 0; p < 4; p++) {
                uint32_t kh[4], kl[4];
                ldsm4(kh, sb + AT_KH + (p * 16 + lr) * AT_PITCH + ks * 32 + lkb);
                ldsm4(kl, sb + AT_KL + (p * 16 + lr) * AT_PITCH + ks * 32 + lkb);
                mma16816(sc[2 * p],     qh, kh[0], kh[2]);
                mma16816(sc[2 * p],     qh, kl[0], kl[2]);
                mma16816(sc[2 * p],     ql, kh[0], kh[2]);
                mma16816(sc[2 * p + 1], qh, kh[1], kh[3]);
                mma16816(sc[2 * p + 1], qh, kl[1], kl[3]);
                mma16816(sc[2 * p + 1], ql, kh[1], kh[3]);
            }
        }
    }

    const float scale = 0.04419417382415922f;
    float mx0 = -1e30f, mx1 = -1e30f;
    #pragma unroll
    for (int nf = 0; nf < 8; nf++) {
        #pragma unroll
        for (int q = 0; q < 4; q++) sc[nf][q] *= scale;
        mx0 = fmaxf(mx0, fmaxf(sc[nf][0], sc[nf][1]));
        mx1 = fmaxf(mx1, fmaxf(sc[nf][2], sc[nf][3]));
    }
    mx0 = fmaxf(mx0, __shfl_xor_sync(0xffffffffu, mx0, 1));
    mx0 = fmaxf(mx0, __shfl_xor_sync(0xffffffffu, mx0, 2));
    mx1 = fmaxf(mx1, __shfl_xor_sync(0xffffffffu, mx1, 1));
    mx1 = fmaxf(mx1, __shfl_xor_sync(0xffffffffu, mx1, 2));

    float s0 = 0.f, s1 = 0.f;
    #pragma unroll
    for (int nf = 0; nf < 8; nf++) {
        sc[nf][0] = __expf(sc[nf][0] - mx0); s0 += sc[nf][0];
        sc[nf][1] = __expf(sc[nf][1] - mx0); s0 += sc[nf][1];
        sc[nf][2] = __expf(sc[nf][2] - mx1); s1 += sc[nf][2];
        sc[nf][3] = __expf(sc[nf][3] - mx1); s1 += sc[nf][3];
    }
    s0 += __shfl_xor_sync(0xffffffffu, s0, 1);
    s0 += __shfl_xor_sync(0xffffffffu, s0, 2);
    s1 += __shfl_xor_sync(0xffffffffu, s1, 1);
    s1 += __shfl_xor_sync(0xffffffffu, s1, 2);
    const float inv0 = 1.f / s0, inv1 = 1.f / s1;

    uint32_t pa[4][4];
    #pragma unroll
    for (int j = 0; j < 4; j++) {
        pa[j][0] = packh2(sc[2 * j][0] * inv0,     sc[2 * j][1] * inv0);
        pa[j][1] = packh2(sc[2 * j][2] * inv1,     sc[2 * j][3] * inv1);
        pa[j][2] = packh2(sc[2 * j + 1][0] * inv0, sc[2 * j + 1][1] * inv0);
        pa[j][3] = packh2(sc[2 * j + 1][2] * inv1, sc[2 * j + 1][3] * inv1);
    }

    const int prow0 = perm[head * TLEN + wm * 16 + (lid >> 2)];
    const int prow8 = perm[head * TLEN + wm * 16 + (lid >> 2) + 8];
    const size_t obase0 = ((size_t)b * SEQ + prow0) * HDIM;
    const size_t obase8 = ((size_t)b * SEQ + prow8) * HDIM;

    for (int hcb = 0; hcb < 4; hcb++) {
        const int hc = hcb * 128;
        __syncthreads();
        {
            const __half* srcs[2] = {g_Vh + tokbase * HDIM, g_Vl + tokbase * HDIM};
            const uint32_t dsts[2] = {sb + AT_VH, sb + AT_VL};
            #pragma unroll
            for (int t = 0; t < 2; t++) {
                #pragma unroll
                for (int i = 0; i < 8; i++) {
                    int idx = tid + i * 128;
                    int r = idx >> 4, cg = idx & 15;
                    cp16(dsts[t] + r * AT_PITCH + cg * 16,
                         srcs[t] + (size_t)r * HDIM + hc + cg * 8);
                }
            }
            cp_commit(); cp_wait0();
        }
        __syncthreads();

        float o[16][4];
        #pragma unroll
        for (int i = 0; i < 16; i++)
            #pragma unroll
            for (int q = 0; q < 4; q++) o[i][q] = 0.f;

        #pragma unroll
        for (int j = 0; j < 4; j++) {
            #pragma unroll
            for (int nf2 = 0; nf2 < 8; nf2++) {
                const uint32_t coff = (nf2 * 16 + ((lid >> 4) & 1) * 8) * 2;
                uint32_t vh[4], vl[4];
                ldsm4t(vh, sb + AT_VH + (j * 16 + lr) * AT_PITCH + coff);
                ldsm4t(vl, sb + AT_VL + (j * 16 + lr) * AT_PITCH + coff);
                mma16816(o[2 * nf2],     pa[j], vh[0], vh[1]);
                mma16816(o[2 * nf2],     pa[j], vl[0], vl[1]);
                mma16816(o[2 * nf2 + 1], pa[j], vh[2], vh[3]);
                mma16816(o[2 * nf2 + 1], pa[j], vl[2], vl[3]);
            }
        }

        #pragma unroll
        for (int nf = 0; nf < 16; nf++) {
            const int col = hc + nf * 8 + (lid & 3) * 2;
            *(uint32_t*)(g_x16 + obase0 + col) = packh2(o[nf][0], o[nf][1]);
            *(uint32_t*)(g_x16 + obase8 + col) = packh2(o[nf][2], o[nf][3]);
        }
    }
}

// ---------------------------------------------------------------------------
extern "C" void kernel_launch(void* const* d_in, const int* in_sizes, int n_in,
                              void* d_out, int out_size)
{
    const float* x  = (const float*)d_in[0];
    const float* Wq = (const float*)d_in[1];
    const float* bq = (const float*)d_in[2];
    const float* Wk = (const float*)d_in[3];
    const float* bk = (const float*)d_in[4];
    const float* Wv = (const float*)d_in[5];
    const float* bv = (const float*)d_in[6];
    const float* Wo = (const float*)d_in[7];
    const float* bo = (const float*)d_in[8];
    const int* perm = (const int*)d_in[9];
    float* out = (float*)d_out;

    __half *x16, *Wh, *Qh, *Ql, *Kh, *Kl, *Vh, *Vl;
    cudaGetSymbolAddress((void**)&x16, g_x16);
    cudaGetSymbolAddress((void**)&Wh,  g_Wh);
    cudaGetSymbolAddress((void**)&Qh,  g_Qh);
    cudaGetSymbolAddress((void**)&Ql,  g_Ql);
    cudaGetSymbolAddress((void**)&Kh,  g_Kh);
    cudaGetSymbolAddress((void**)&Kl,  g_Kl);
    cudaGetSymbolAddress((void**)&Vh,  g_Vh);
    cudaGetSymbolAddress((void**)&Vl,  g_Vl);

    cudaFuncSetAttribute(mma_gemm_kernel,
                         cudaFuncAttributeMaxDynamicSharedMemorySize, SMEM_REQ);
    cudaFuncSetAttribute(attn_kernel,
                         cudaFuncAttributeMaxDynamicSharedMemorySize, ATTN_SMEM);

    const int WN  = HDIM * HDIM;
    const int XN4 = (NROWS * HDIM) / 4;
    const int WN4 = WN / 4;

    conv_x_kernel<<<(XN4 + 255) / 256, 256>>>(x, x16, XN4);
    conv_x_kernel<<<(WN4 + 255) / 256, 256>>>(Wq, Wh + 0 * WN, WN4);
    conv_x_kernel<<<(WN4 + 255) / 256, 256>>>(Wk, Wh + 1 * WN, WN4);
    conv_x_kernel<<<(WN4 + 255) / 256, 256>>>(Wv, Wh + 2 * WN, WN4);
    conv_x_kernel<<<(WN4 + 255) / 256, 256>>>(Wo, Wh + 3 * WN, WN4);

    dim3 gg(HDIM / BN, NROWS / BM);       // (4, 256)

    // QKV projections -> split fp16 outputs (permuted row order)
    mma_gemm_kernel<<<gg, 256, SMEM_REQ>>>(x16, Wh + 0 * WN, bq,
                                           nullptr, Qh, Ql, perm, 1);
    mma_gemm_kernel<<<gg, 256, SMEM_REQ>>>(x16, Wh + 1 * WN, bk,
                                           nullptr, Kh, Kl, perm, 1);
    mma_gemm_kernel<<<gg, 256, SMEM_REQ>>>(x16, Wh + 2 * WN, bv,
                                           nullptr, Vh, Vl, perm, 1);

    // tensorized attention -> g_x16 (fp16, un-permuted)
    attn_kernel<<<dim3(NHEAD, BATCH), 128, ATTN_SMEM>>>(perm);

    // output projection -> fp32 out
    mma_gemm_kernel<<<gg, 256, SMEM_REQ>>>(x16, Wh + 3 * WN, bo,
                                           out, nullptr, nullptr, perm, 0);
}

// round 8
// speedup vs baseline: 3.0406x; 1.1886x over previous
#include <cuda_runtime.h>
#include <cuda_fp16.h>
#include <cstdint>

#define BATCH 8
#define SEQ   4096
#define HDIM  512
#define NROWS (BATCH * SEQ)   // 32768
#define NHEAD 64
#define TLEN  64

#define BM 128
#define BN 128
#define BK 32
#define NCHUNK (HDIM / BK)    // 16
#define WN (HDIM * HDIM)

#define ROWB 80               // GEMM smem row stride bytes (32 fp16 + pad)

// GEMM smem layout (single-split A and B, double buffered)
#define SMP_PRM   0
#define SMP_A     512
#define A_BUF_STRIDE 10240
#define SMP_B     (512 + 20480)
#define B_BUF_STRIDE 10240
#define SMEM_REQ  (512 + 20480 + 20480)    // 41472

// attn smem: 4 tile slots of 64 rows x 272B pitch
#define AT_PITCH  272
#define AT_TILE   (64 * AT_PITCH)          // 17408
#define ATTN_SMEM (4 * AT_TILE)            // 69632

// ---------------- scratch (device globals; allocation-free) ----------------
__device__ __half g_QKV[3 * NROWS * HDIM];   // Q, K, V (fp16, permuted order)
__device__ __half g_x16[NROWS * HDIM];       // fp16 activations (x, then attn out)
__device__ __half g_Wh[4 * HDIM * HDIM];     // fp16 weights
__device__ float  g_bias[3 * HDIM];          // bq, bk, bv contiguous

// ---------------- helpers ----------------
__device__ __forceinline__ uint32_t smem_to_u32(const void* p) {
    uint32_t a;
    asm("{ .reg .u64 t; cvta.to.shared.u64 t, %1; cvt.u32.u64 %0, t; }"
        : "=r"(a) : "l"(p));
    return a;
}
__device__ __forceinline__ void cp16(uint32_t dst, const void* src) {
    asm volatile("cp.async.cg.shared.global [%0], [%1], 16;"
                 :: "r"(dst), "l"(src) : "memory");
}
__device__ __forceinline__ void cp_commit() {
    asm volatile("cp.async.commit_group;" ::: "memory");
}
__device__ __forceinline__ void cp_wait1() {
    asm volatile("cp.async.wait_group 1;" ::: "memory");
}
__device__ __forceinline__ void cp_wait0() {
    asm volatile("cp.async.wait_group 0;" ::: "memory");
}
__device__ __forceinline__ void ldsm4(uint32_t* r, uint32_t addr) {
    asm volatile("ldmatrix.sync.aligned.m8n8.x4.shared.b16 {%0,%1,%2,%3}, [%4];"
                 : "=r"(r[0]), "=r"(r[1]), "=r"(r[2]), "=r"(r[3]) : "r"(addr));
}
__device__ __forceinline__ void ldsm4t(uint32_t* r, uint32_t addr) {
    asm volatile("ldmatrix.sync.aligned.m8n8.x4.trans.shared.b16 {%0,%1,%2,%3}, [%4];"
                 : "=r"(r[0]), "=r"(r[1]), "=r"(r[2]), "=r"(r[3]) : "r"(addr));
}
__device__ __forceinline__ void mma16816(float* d, const uint32_t* a,
                                         const uint32_t b0, const uint32_t b1) {
    asm volatile(
        "mma.sync.aligned.m16n8k16.row.col.f32.f16.f16.f32 "
        "{%0,%1,%2,%3}, {%4,%5,%6,%7}, {%8,%9}, {%0,%1,%2,%3};"
        : "+f"(d[0]), "+f"(d[1]), "+f"(d[2]), "+f"(d[3])
        : "r"(a[0]), "r"(a[1]), "r"(a[2]), "r"(a[3]), "r"(b0), "r"(b1));
}
__device__ __forceinline__ uint32_t packh2(float a, float b) {
    __half2 h = __floats2half2_rn(a, b);
    return *(uint32_t*)&h;
}

// ---------------------------------------------------------------------------
// conversions
// ---------------------------------------------------------------------------
__global__ void __launch_bounds__(256) conv_x_kernel(
    const float* __restrict__ src, __half* __restrict__ h, int n4)
{
    int i = blockIdx.x * 256 + threadIdx.x;
    if (i >= n4) return;
    float4 v = ((const float4*)src)[i];
    uint2 o;
    o.x = packh2(v.x, v.y);
    o.y = packh2(v.z, v.w);
    ((uint2*)h)[i] = o;
}

__global__ void __launch_bounds__(256) conv_w4_kernel(
    const float* __restrict__ s0, const float* __restrict__ s1,
    const float* __restrict__ s2, const float* __restrict__ s3,
    __half* __restrict__ dst, int n4)
{
    const int w = blockIdx.y;
    const float* s = (w == 0) ? s0 : (w == 1) ? s1 : (w == 2) ? s2 : s3;
    int i = blockIdx.x * 256 + threadIdx.x;
    if (i >= n4) return;
    float4 v = ((const float4*)s)[i];
    uint2 o;
    o.x = packh2(v.x, v.y);
    o.y = packh2(v.z, v.w);
    ((uint2*)(dst + (size_t)w * WN))[i] = o;
}

// ---------------------------------------------------------------------------
// single-product fp16 GEMM: out[m,n] = sum_k A[rowmap(m),k]*W[n,k] + bias[n]
// blockIdx.z selects the weight/bias/output slice (fused QKV: z = 0..2).
// Epilogue: fp32 out (outf, z=0 only) OR fp16 out (outhBase + z slice).
// ---------------------------------------------------------------------------
__global__ void __launch_bounds__(256, 2) mma_gemm_kernel(
    const __half* __restrict__ A16, const __half* __restrict__ Wbase,
    const float* __restrict__ biasBase, float* __restrict__ outf,
    __half* __restrict__ outhBase, const int* __restrict__ perm, int use_perm)
{
    extern __shared__ char smem[];
    const uint32_t sb = smem_to_u32(smem);
    int* prm = (int*)(smem + SMP_PRM);

    const int z = blockIdx.z;
    const __half* Bh = Wbase + (size_t)z * WN;
    const float* bias = biasBase + z * HDIM;

    const int tid = threadIdx.x;
    const int lid = tid & 31;
    const int wid = tid >> 5;
    const int wm  = wid & 1;
    const int wn  = wid >> 1;

    const int n0 = blockIdx.x * BN;
    const int m0 = blockIdx.y * BM;
    const int b  = m0 / SEQ;
    const int i0 = m0 % SEQ;

    if (tid < BM)
        prm[tid] = b * SEQ + (use_perm ? perm[i0 + tid] : (i0 + tid));
    __syncthreads();

    const int r0 = tid >> 2;
    const int g  = tid & 3;
    const int pr0 = prm[r0];
    const int pr1 = prm[r0 + 64];
    const __half* sA0 = A16 + (size_t)pr0 * HDIM + g * 8;
    const __half* sA1 = A16 + (size_t)pr1 * HDIM + g * 8;
    const __half* sB0 = Bh + (size_t)(n0 + r0) * HDIM + g * 8;
    const __half* sB1 = Bh + (size_t)(n0 + r0 + 64) * HDIM + g * 8;
    const uint32_t d0 = (uint32_t)r0 * ROWB + g * 16;
    const uint32_t d1 = d0 + 64 * ROWB;

    const uint32_t lrow = (lid & 15);
    const uint32_t lk   = ((lid >> 4) & 1) * 16;
    const uint32_t aOff = (wm * 64 + lrow) * ROWB + lk;
    const uint32_t bOff = (wn * 32 + lrow) * ROWB + lk;

    float acc[4][4][4];
    #pragma unroll
    for (int i = 0; i < 4; i++)
        #pragma unroll
        for (int j = 0; j < 4; j++)
            #pragma unroll
            for (int q = 0; q < 4; q++) acc[i][j][q] = 0.f;

    {
        const uint32_t aB = sb + SMP_A;
        const uint32_t bB = sb + SMP_B;
        cp16(aB + d0, sA0); cp16(aB + d1, sA1);
        cp16(bB + d0, sB0); cp16(bB + d1, sB1);
        cp_commit();
    }

    for (int c = 0; c < NCHUNK; c++) {
        const int buf = c & 1;
        if (c + 1 < NCHUNK) {
            const size_t ko = (size_t)(c + 1) * BK;
            const uint32_t aB = sb + SMP_A + (1 - buf) * A_BUF_STRIDE;
            const uint32_t bB = sb + SMP_B + (1 - buf) * B_BUF_STRIDE;
            cp16(aB + d0, sA0 + ko); cp16(aB + d1, sA1 + ko);
            cp16(bB + d0, sB0 + ko); cp16(bB + d1, sB1 + ko);
            cp_commit();
            cp_wait1();
        } else {
            cp_wait0();
        }
        __syncthreads();

        const uint32_t aB = sb + SMP_A + buf * A_BUF_STRIDE;
        const uint32_t bB = sb + SMP_B + buf * B_BUF_STRIDE;

        #pragma unroll
        for (int ks = 0; ks < 2; ks++) {
            uint32_t ah[4][4];
            #pragma unroll
            for (int mf = 0; mf < 4; mf++)
                ldsm4(ah[mf], aB + aOff + mf * (16 * ROWB) + ks * 32);
            #pragma unroll
            for (int p = 0; p < 2; p++) {
                uint32_t tb[4];
                ldsm4(tb, bB + bOff + p * (16 * ROWB) + ks * 32);
                #pragma unroll
                for (int mf = 0; mf < 4; mf++) {
                    mma16816(acc[mf][2 * p],     ah[mf], tb[0], tb[2]);
                    mma16816(acc[mf][2 * p + 1], ah[mf], tb[1], tb[3]);
                }
            }
        }
        __syncthreads();
    }

    // ---- epilogue ----
    __half* outh = outhBase ? (outhBase + (size_t)z * NROWS * HDIM) : nullptr;
    #pragma unroll
    for (int mf = 0; mf < 4; mf++) {
        const int row = m0 + wm * 64 + mf * 16 + (lid >> 2);
        #pragma unroll
        for (int nf = 0; nf < 4; nf++) {
            const int col = n0 + wn * 32 + nf * 8 + (lid & 3) * 2;
            const float2 bb = *(const float2*)(bias + col);
            float v00 = acc[mf][nf][0] + bb.x, v01 = acc[mf][nf][1] + bb.y;
            float v10 = acc[mf][nf][2] + bb.x, v11 = acc[mf][nf][3] + bb.y;
            if (outf) {
                *(float2*)(outf + (size_t)row * HDIM + col) = make_float2(v00, v01);
                *(float2*)(outf + (size_t)(row + 8) * HDIM + col) = make_float2(v10, v11);
            } else {
                *(uint32_t*)(outh + (size_t)row * HDIM + col)       = packh2(v00, v01);
                *(uint32_t*)(outh + (size_t)(row + 8) * HDIM + col) = packh2(v10, v11);
            }
        }
    }
}

// ---------------------------------------------------------------------------
// Tensorized block attention, single-fp16 Q/K/V, double-buffered staging.
// 1 block per (head,batch), 128 threads / 4 warps; warp wm owns rows wm*16..+15.
// ---------------------------------------------------------------------------
__global__ void __launch_bounds__(128) attn_kernel(const int* __restrict__ perm)
{
    extern __shared__ char smem[];
    const uint32_t sb = smem_to_u32(smem);

    const int head = blockIdx.x;
    const int b    = blockIdx.y;
    const int tid  = threadIdx.x;
    const int lid  = tid & 31;
    const int wm   = tid >> 5;

    const size_t tokbase = ((size_t)b * SEQ + head * TLEN) * HDIM;
    const __half* Qg = g_QKV + 0 * (size_t)NROWS * HDIM + tokbase;
    const __half* Kg = g_QKV + 1 * (size_t)NROWS * HDIM + tokbase;
    const __half* Vg = g_QKV + 2 * (size_t)NROWS * HDIM + tokbase;

    const uint32_t lr = lid & 15;
    const uint32_t lkb = ((lid >> 4) & 1) * 16;

    // tile stagers: 64 rows x 128 halfs, 8 cp16 per thread per tile
    #define STAGE2(dstq, dstk, srcq, srck, hc) do { \
        _Pragma("unroll") \
        for (int i_ = 0; i_ < 8; i_++) { \
            int idx_ = tid + i_ * 128; \
            int r_ = idx_ >> 4, cg_ = idx_ & 15; \
            cp16((dstq) + r_ * AT_PITCH + cg_ * 16, (srcq) + (size_t)r_ * HDIM + (hc) + cg_ * 8); \
            cp16((dstk) + r_ * AT_PITCH + cg_ * 16, (srck) + (size_t)r_ * HDIM + (hc) + cg_ * 8); \
        } } while (0)
    #define STAGE1(dstv, srcv, hc) do { \
        _Pragma("unroll") \
        for (int i_ = 0; i_ < 8; i_++) { \
            int idx_ = tid + i_ * 128; \
            int r_ = idx_ >> 4, cg_ = idx_ & 15; \
            cp16((dstv) + r_ * AT_PITCH + cg_ * 16, (srcv) + (size_t)r_ * HDIM + (hc) + cg_ * 8); \
        } } while (0)

    // ---- Phase 1: scores (64x64), double-buffered QK staging ----
    float sc[8][4];
    #pragma unroll
    for (int i = 0; i < 8; i++)
        #pragma unroll
        for (int q = 0; q < 4; q++) sc[i][q] = 0.f;

    STAGE2(sb + 0 * AT_TILE, sb + 1 * AT_TILE, Qg, Kg, 0);
    cp_commit();

    for (int hcb = 0; hcb < 4; hcb++) {
        if (hcb < 3) {
            const uint32_t s = ((hcb + 1) & 1) * 2;
            STAGE2(sb + s * AT_TILE, sb + (s + 1) * AT_TILE, Qg, Kg, (hcb + 1) * 128);
            cp_commit();
            cp_wait1();
        } else {
            // prefetch V chunk 0 into slot 0 (free since chunk-2 compute ended)
            STAGE1(sb + 0 * AT_TILE, Vg, 0);
            cp_commit();
            cp_wait1();
        }
        __syncthreads();

        const uint32_t qb = sb + ((hcb & 1) * 2) * AT_TILE;
        const uint32_t kb = qb + AT_TILE;
        #pragma unroll
        for (int ks = 0; ks < 8; ks++) {
            uint32_t qh[4];
            ldsm4(qh, qb + (wm * 16 + lr) * AT_PITCH + ks * 32 + lkb);
            #pragma unroll
            for (int p = 0; p < 4; p++) {
                uint32_t kh[4];
                ldsm4(kh, kb + (p * 16 + lr) * AT_PITCH + ks * 32 + lkb);
                mma16816(sc[2 * p],     qh, kh[0], kh[2]);
                mma16816(sc[2 * p + 1], qh, kh[1], kh[3]);
            }
        }
        __syncthreads();
    }

    // ---- Softmax (rows r = wm*16 + lid>>2 and +8), overlapped with V0 load ----
    const float scale = 0.04419417382415922f;   // 1/sqrt(512)
    float mx0 = -1e30f, mx1 = -1e30f;
    #pragma unroll
    for (int nf = 0; nf < 8; nf++) {
        #pragma unroll
        for (int q = 0; q < 4; q++) sc[nf][q] *= scale;
        mx0 = fmaxf(mx0, fmaxf(sc[nf][0], sc[nf][1]));
        mx1 = fmaxf(mx1, fmaxf(sc[nf][2], sc[nf][3]));
    }
    mx0 = fmaxf(mx0, __shfl_xor_sync(0xffffffffu, mx0, 1));
    mx0 = fmaxf(mx0, __shfl_xor_sync(0xffffffffu, mx0, 2));
    mx1 = fmaxf(mx1, __shfl_xor_sync(0xffffffffu, mx1, 1));
    mx1 = fmaxf(mx1, __shfl_xor_sync(0xffffffffu, mx1, 2));

    float s0 = 0.f, s1 = 0.f;
    #pragma unroll
    for (int nf = 0; nf < 8; nf++) {
        sc[nf][0] = __expf(sc[nf][0] - mx0); s0 += sc[nf][0];
        sc[nf][1] = __expf(sc[nf][1] - mx0); s0 += sc[nf][1];
        sc[nf][2] = __expf(sc[nf][2] - mx1); s1 += sc[nf][2];
        sc[nf][3] = __expf(sc[nf][3] - mx1); s1 += sc[nf][3];
    }
    s0 += __shfl_xor_sync(0xffffffffu, s0, 1);
    s0 += __shfl_xor_sync(0xffffffffu, s0, 2);
    s1 += __shfl_xor_sync(0xffffffffu, s1, 1);
    s1 += __shfl_xor_sync(0xffffffffu, s1, 2);
    const float inv0 = 1.f / s0, inv1 = 1.f / s1;

    // P fragments as fp16 A-operands (kstep j covers tokens 16j..16j+15)
    uint32_t pa[4][4];
    #pragma unroll
    for (int j = 0; j < 4; j++) {
        pa[j][0] = packh2(sc[2 * j][0] * inv0,     sc[2 * j][1] * inv0);
        pa[j][1] = packh2(sc[2 * j][2] * inv1,     sc[2 * j][3] * inv1);
        pa[j][2] = packh2(sc[2 * j + 1][0] * inv0, sc[2 * j + 1][1] * inv0);
        pa[j][3] = packh2(sc[2 * j + 1][2] * inv1, sc[2 * j + 1][3] * inv1);
    }

    const int prow0 = perm[head * TLEN + wm * 16 + (lid >> 2)];
    const int prow8 = perm[head * TLEN + wm * 16 + (lid >> 2) + 8];
    const size_t obase0 = ((size_t)b * SEQ + prow0) * HDIM;
    const size_t obase8 = ((size_t)b * SEQ + prow8) * HDIM;

    // ---- Phase 2: O = P V, double-buffered V staging (slots 0/1) ----
    for (int hcb = 0; hcb < 4; hcb++) {
        if (hcb < 3) {
            STAGE1(sb + ((hcb + 1) & 1) * AT_TILE, Vg, (hcb + 1) * 128);
            cp_commit();
            cp_wait1();
        } else {
            cp_wait0();
        }
        __syncthreads();

        const uint32_t vb = sb + (hcb & 1) * AT_TILE;
        float o[16][4];
        #pragma unroll
        for (int i = 0; i < 16; i++)
            #pragma unroll
            for (int q = 0; q < 4; q++) o[i][q] = 0.f;

        #pragma unroll
        for (int j = 0; j < 4; j++) {
            #pragma unroll
            for (int nf2 = 0; nf2 < 8; nf2++) {
                const uint32_t coff = (nf2 * 16 + ((lid >> 4) & 1) * 8) * 2;
                uint32_t vh[4];
                ldsm4t(vh, vb + (j * 16 + lr) * AT_PITCH + coff);
                mma16816(o[2 * nf2],     pa[j], vh[0], vh[1]);
                mma16816(o[2 * nf2 + 1], pa[j], vh[2], vh[3]);
            }
        }

        const int hc = hcb * 128;
        #pragma unroll
        for (int nf = 0; nf < 16; nf++) {
            const int col = hc + nf * 8 + (lid & 3) * 2;
            *(uint32_t*)(g_x16 + obase0 + col) = packh2(o[nf][0], o[nf][1]);
            *(uint32_t*)(g_x16 + obase8 + col) = packh2(o[nf][2], o[nf][3]);
        }
        __syncthreads();
    }
    #undef STAGE2
    #undef STAGE1
}

// ---------------------------------------------------------------------------
extern "C" void kernel_launch(void* const* d_in, const int* in_sizes, int n_in,
                              void* d_out, int out_size)
{
    const float* x  = (const float*)d_in[0];
    const float* Wq = (const float*)d_in[1];
    const float* bq = (const float*)d_in[2];
    const float* Wk = (const float*)d_in[3];
    const float* bk = (const float*)d_in[4];
    const float* Wv = (const float*)d_in[5];
    const float* bv = (const float*)d_in[6];
    const float* Wo = (const float*)d_in[7];
    const float* bo = (const float*)d_in[8];
    const int* perm = (const int*)d_in[9];
    float* out = (float*)d_out;

    __half *x16, *Wh, *qkv;
    float* biasd;
    cudaGetSymbolAddress((void**)&x16,   g_x16);
    cudaGetSymbolAddress((void**)&Wh,    g_Wh);
    cudaGetSymbolAddress((void**)&qkv,   g_QKV);
    cudaGetSymbolAddress((void**)&biasd, g_bias);

    cudaFuncSetAttribute(mma_gemm_kernel,
                         cudaFuncAttributeMaxDynamicSharedMemorySize, SMEM_REQ);
    cudaFuncSetAttribute(attn_kernel,
                         cudaFuncAttributeMaxDynamicSharedMemorySize, ATTN_SMEM);

    const int XN4 = (NROWS * HDIM) / 4;   // 4194304
    const int WN4 = WN / 4;               // 65536

    // bias pack (device-to-device async copies are graph-capturable)
    cudaMemcpyAsync(biasd + 0 * HDIM, bq, HDIM * sizeof(float), cudaMemcpyDeviceToDevice);
    cudaMemcpyAsync(biasd + 1 * HDIM, bk, HDIM * sizeof(float), cudaMemcpyDeviceToDevice);
    cudaMemcpyAsync(biasd + 2 * HDIM, bv, HDIM * sizeof(float), cudaMemcpyDeviceToDevice);

    // conversions
    conv_x_kernel<<<(XN4 + 255) / 256, 256>>>(x, x16, XN4);
    conv_w4_kernel<<<dim3((WN4 + 255) / 256, 4), 256>>>(Wq, Wk, Wv, Wo, Wh, WN4);

    // fused QKV projections (grid.z = 0..2) -> g_QKV fp16 (permuted rows)
    mma_gemm_kernel<<<dim3(HDIM / BN, NROWS / BM, 3), 256, SMEM_REQ>>>(
        x16, Wh, biasd, nullptr, qkv, perm, 1);

    // tensorized attention -> g_x16 (fp16, un-permuted)
    attn_kernel<<<dim3(NHEAD, BATCH), 128, ATTN_SMEM>>>(perm);

    // output projection -> fp32 out
    mma_gemm_kernel<<<dim3(HDIM / BN, NROWS / BM, 1), 256, SMEM_REQ>>>(
        x16, Wh + 3 * (size_t)WN, bo, out, nullptr, perm, 0);
}

// round 9
// speedup vs baseline: 3.1423x; 1.0334x over previous
#include <cuda_runtime.h>
#include <cuda_fp16.h>
#include <cstdint>

#define BATCH 8
#define SEQ   4096
#define HDIM  512
#define NROWS (BATCH * SEQ)   // 32768
#define NHEAD 64
#define TLEN  64

#define BM 128
#define BN 128
#define BK 32
#define NCHUNK (HDIM / BK)    // 16
#define WN (HDIM * HDIM)

#define ROWB 80               // GEMM smem row stride bytes (32 fp16 + pad)

// GEMM smem layout (single-split A and B, double buffered)
#define SMP_PRM   0
#define SMP_A     512
#define A_BUF_STRIDE 10240
#define SMP_B     (512 + 20480)
#define B_BUF_STRIDE 10240
#define SMEM_REQ  (512 + 20480 + 20480)    // 41472

// attn smem: 4 tile slots (64 rows x 272B) + P (64 x 144B) + reductions
#define AT_PITCH  272
#define AT_TILE   (64 * AT_PITCH)          // 17408
#define P_OFF     (4 * AT_TILE)            // 69632
#define P_PITCH   144
#define RED_OFF   (P_OFF + 64 * P_PITCH)   // 78848
#define ATTN_SMEM (RED_OFF + 1024)         // 79872

// conv grid split
#define XN4 ((NROWS * HDIM) / 4)           // 4194304
#define WN4 (WN / 4)                       // 65536
#define XB  (XN4 / 256)                    // 16384
#define WB  (WN4 / 256)                    // 256

// ---------------- scratch (device globals; allocation-free) ----------------
__device__ __half g_QKV[3 * NROWS * HDIM];   // Q, K, V (fp16, permuted order)
__device__ __half g_x16[NROWS * HDIM];       // fp16 activations (x, then attn out)
__device__ __half g_Wh[4 * HDIM * HDIM];     // fp16 weights

// ---------------- helpers ----------------
__device__ __forceinline__ uint32_t smem_to_u32(const void* p) {
    uint32_t a;
    asm("{ .reg .u64 t; cvta.to.shared.u64 t, %1; cvt.u32.u64 %0, t; }"
        : "=r"(a) : "l"(p));
    return a;
}
__device__ __forceinline__ void cp16(uint32_t dst, const void* src) {
    asm volatile("cp.async.cg.shared.global [%0], [%1], 16;"
                 :: "r"(dst), "l"(src) : "memory");
}
__device__ __forceinline__ void cp_commit() {
    asm volatile("cp.async.commit_group;" ::: "memory");
}
__device__ __forceinline__ void cp_wait1() {
    asm volatile("cp.async.wait_group 1;" ::: "memory");
}
__device__ __forceinline__ void cp_wait0() {
    asm volatile("cp.async.wait_group 0;" ::: "memory");
}
__device__ __forceinline__ void ldsm4(uint32_t* r, uint32_t addr) {
    asm volatile("ldmatrix.sync.aligned.m8n8.x4.shared.b16 {%0,%1,%2,%3}, [%4];"
                 : "=r"(r[0]), "=r"(r[1]), "=r"(r[2]), "=r"(r[3]) : "r"(addr));
}
__device__ __forceinline__ void ldsm4t(uint32_t* r, uint32_t addr) {
    asm volatile("ldmatrix.sync.aligned.m8n8.x4.trans.shared.b16 {%0,%1,%2,%3}, [%4];"
                 : "=r"(r[0]), "=r"(r[1]), "=r"(r[2]), "=r"(r[3]) : "r"(addr));
}
__device__ __forceinline__ void mma16816(float* d, const uint32_t* a,
                                         const uint32_t b0, const uint32_t b1) {
    asm volatile(
        "mma.sync.aligned.m16n8k16.row.col.f32.f16.f16.f32 "
        "{%0,%1,%2,%3}, {%4,%5,%6,%7}, {%8,%9}, {%0,%1,%2,%3};"
        : "+f"(d[0]), "+f"(d[1]), "+f"(d[2]), "+f"(d[3])
        : "r"(a[0]), "r"(a[1]), "r"(a[2]), "r"(a[3]), "r"(b0), "r"(b1));
}
__device__ __forceinline__ uint32_t packh2(float a, float b) {
    __half2 h = __floats2half2_rn(a, b);
    return *(uint32_t*)&h;
}

// ---------------------------------------------------------------------------
// fused conversion: x (XB blocks) then Wq,Wk,Wv,Wo (WB blocks each) -> fp16
// ---------------------------------------------------------------------------
__global__ void __launch_bounds__(256) conv_all_kernel(
    const float* __restrict__ x,
    const float* __restrict__ Wq, const float* __restrict__ Wk,
    const float* __restrict__ Wv, const float* __restrict__ Wo,
    __half* __restrict__ x16, __half* __restrict__ Wh)
{
    const int bid = blockIdx.x;
    const float* src;
    __half* dst;
    int i;
    if (bid < XB) {
        src = x; dst = x16; i = bid * 256 + threadIdx.x;
    } else {
        const int w = (bid - XB) / WB;
        const int lb = (bid - XB) - w * WB;
        src = (w == 0) ? Wq : (w == 1) ? Wk : (w == 2) ? Wv : Wo;
        dst = Wh + (size_t)w * WN;
        i = lb * 256 + threadIdx.x;
    }
    float4 v = ((const float4*)src)[i];
    uint2 o;
    o.x = packh2(v.x, v.y);
    o.y = packh2(v.z, v.w);
    ((uint2*)dst)[i] = o;
}

// ---------------------------------------------------------------------------
// single-product fp16 GEMM: out[m,n] = sum_k A[rowmap(m),k]*W[n,k] + bias[n]
// blockIdx.z selects weight/bias/output slice (fused QKV: z = 0..2).
// ---------------------------------------------------------------------------
__global__ void __launch_bounds__(256, 2) mma_gemm_kernel(
    const __half* __restrict__ A16, const __half* __restrict__ Wbase,
    const float* __restrict__ b0p, const float* __restrict__ b1p,
    const float* __restrict__ b2p, float* __restrict__ outf,
    __half* __restrict__ outhBase, const int* __restrict__ perm, int use_perm)
{
    extern __shared__ char smem[];
    const uint32_t sb = smem_to_u32(smem);
    int* prm = (int*)(smem + SMP_PRM);

    const int z = blockIdx.z;
    const __half* Bh = Wbase + (size_t)z * WN;
    const float* bias = (z == 0) ? b0p : (z == 1) ? b1p : b2p;

    const int tid = threadIdx.x;
    const int lid = tid & 31;
    const int wid = tid >> 5;
    const int wm  = wid & 1;
    const int wn  = wid >> 1;

    const int n0 = blockIdx.x * BN;
    const int m0 = blockIdx.y * BM;
    const int b  = m0 / SEQ;
    const int i0 = m0 % SEQ;

    if (tid < BM)
        prm[tid] = b * SEQ + (use_perm ? perm[i0 + tid] : (i0 + tid));
    __syncthreads();

    const int r0 = tid >> 2;
    const int g  = tid & 3;
    const int pr0 = prm[r0];
    const int pr1 = prm[r0 + 64];
    const __half* sA0 = A16 + (size_t)pr0 * HDIM + g * 8;
    const __half* sA1 = A16 + (size_t)pr1 * HDIM + g * 8;
    const __half* sB0 = Bh + (size_t)(n0 + r0) * HDIM + g * 8;
    const __half* sB1 = Bh + (size_t)(n0 + r0 + 64) * HDIM + g * 8;
    const uint32_t d0 = (uint32_t)r0 * ROWB + g * 16;
    const uint32_t d1 = d0 + 64 * ROWB;

    const uint32_t lrow = (lid & 15);
    const uint32_t lk   = ((lid >> 4) & 1) * 16;
    const uint32_t aOff = (wm * 64 + lrow) * ROWB + lk;
    const uint32_t bOff = (wn * 32 + lrow) * ROWB + lk;

    float acc[4][4][4];
    #pragma unroll
    for (int i = 0; i < 4; i++)
        #pragma unroll
        for (int j = 0; j < 4; j++)
            #pragma unroll
            for (int q = 0; q < 4; q++) acc[i][j][q] = 0.f;

    {
        const uint32_t aB = sb + SMP_A;
        const uint32_t bB = sb + SMP_B;
        cp16(aB + d0, sA0); cp16(aB + d1, sA1);
        cp16(bB + d0, sB0); cp16(bB + d1, sB1);
        cp_commit();
    }

    for (int c = 0; c < NCHUNK; c++) {
        const int buf = c & 1;
        if (c + 1 < NCHUNK) {
            const size_t ko = (size_t)(c + 1) * BK;
            const uint32_t aB = sb + SMP_A + (1 - buf) * A_BUF_STRIDE;
            const uint32_t bB = sb + SMP_B + (1 - buf) * B_BUF_STRIDE;
            cp16(aB + d0, sA0 + ko); cp16(aB + d1, sA1 + ko);
            cp16(bB + d0, sB0 + ko); cp16(bB + d1, sB1 + ko);
            cp_commit();
            cp_wait1();
        } else {
            cp_wait0();
        }
        __syncthreads();

        const uint32_t aB = sb + SMP_A + buf * A_BUF_STRIDE;
        const uint32_t bB = sb + SMP_B + buf * B_BUF_STRIDE;

        #pragma unroll
        for (int ks = 0; ks < 2; ks++) {
            uint32_t ah[4][4];
            #pragma unroll
            for (int mf = 0; mf < 4; mf++)
                ldsm4(ah[mf], aB + aOff + mf * (16 * ROWB) + ks * 32);
            #pragma unroll
            for (int p = 0; p < 2; p++) {
                uint32_t tb[4];
                ldsm4(tb, bB + bOff + p * (16 * ROWB) + ks * 32);
                #pragma unroll
                for (int mf = 0; mf < 4; mf++) {
                    mma16816(acc[mf][2 * p],     ah[mf], tb[0], tb[2]);
                    mma16816(acc[mf][2 * p + 1], ah[mf], tb[1], tb[3]);
                }
            }
        }
        __syncthreads();
    }

    // ---- epilogue ----
    __half* outh = outhBase ? (outhBase + (size_t)z * NROWS * HDIM) : nullptr;
    #pragma unroll
    for (int mf = 0; mf < 4; mf++) {
        const int row = m0 + wm * 64 + mf * 16 + (lid >> 2);
        #pragma unroll
        for (int nf = 0; nf < 4; nf++) {
            const int col = n0 + wn * 32 + nf * 8 + (lid & 3) * 2;
            const float2 bb = *(const float2*)(bias + col);
            float v00 = acc[mf][nf][0] + bb.x, v01 = acc[mf][nf][1] + bb.y;
            float v10 = acc[mf][nf][2] + bb.x, v11 = acc[mf][nf][3] + bb.y;
            if (outf) {
                *(float2*)(outf + (size_t)row * HDIM + col) = make_float2(v00, v01);
                *(float2*)(outf + (size_t)(row + 8) * HDIM + col) = make_float2(v10, v11);
            } else {
                *(uint32_t*)(outh + (size_t)row * HDIM + col)       = packh2(v00, v01);
                *(uint32_t*)(outh + (size_t)(row + 8) * HDIM + col) = packh2(v10, v11);
            }
        }
    }
}

// ---------------------------------------------------------------------------
// Tensorized block attention: 256 threads / 8 warps.
// Scores: warp grid 4(m)x2(n) — warp (wm,wn2) owns rows wm*16..+15, cols wn2*32..+31.
// P exchanged via smem; AV: warp (wm,wn2) owns rows wm*16..+15, headdim half wn2*64.
// ---------------------------------------------------------------------------
__global__ void __launch_bounds__(256) attn_kernel(const int* __restrict__ perm)
{
    extern __shared__ char smem[];
    const uint32_t sb = smem_to_u32(smem);
    float* red = (float*)(smem + RED_OFF);     // pmax[64][2] then psum[64][2]
    float* pmax = red;
    float* psum = red + 128;

    const int head = blockIdx.x;
    const int b    = blockIdx.y;
    const int tid  = threadIdx.x;
    const int lid  = tid & 31;
    const int wid  = tid >> 5;
    const int wm   = wid & 3;     // row group (16 rows)
    const int wn2  = wid >> 2;    // col/headdim half

    const size_t tokbase = ((size_t)b * SEQ + head * TLEN) * HDIM;
    const __half* Qg = g_QKV + 0 * (size_t)NROWS * HDIM + tokbase;
    const __half* Kg = g_QKV + 1 * (size_t)NROWS * HDIM + tokbase;
    const __half* Vg = g_QKV + 2 * (size_t)NROWS * HDIM + tokbase;

    const uint32_t lr = lid & 15;
    const uint32_t lkb = ((lid >> 4) & 1) * 16;

    // stage one 64x128-half tile with 256 threads (4 cp16 each)
    #define STAGE1(dst, src, hc) do { \
        _Pragma("unroll") \
        for (int i_ = 0; i_ < 4; i_++) { \
            int idx_ = tid + i_ * 256; \
            int r_ = idx_ >> 4, cg_ = idx_ & 15; \
            cp16((dst) + r_ * AT_PITCH + cg_ * 16, (src) + (size_t)r_ * HDIM + (hc) + cg_ * 8); \
        } } while (0)

    // ---- Phase 1: scores, double-buffered QK staging ----
    float sc[4][4];
    #pragma unroll
    for (int i = 0; i < 4; i++)
        #pragma unroll
        for (int q = 0; q < 4; q++) sc[i][q] = 0.f;

    STAGE1(sb + 0 * AT_TILE, Qg, 0);
    STAGE1(sb + 1 * AT_TILE, Kg, 0);
    cp_commit();

    for (int hcb = 0; hcb < 4; hcb++) {
        if (hcb < 3) {
            const uint32_t s = ((hcb + 1) & 1) * 2;
            STAGE1(sb + s * AT_TILE, Qg, (hcb + 1) * 128);
            STAGE1(sb + (s + 1) * AT_TILE, Kg, (hcb + 1) * 128);
            cp_commit();
            cp_wait1();
        } else {
            STAGE1(sb + 0 * AT_TILE, Vg, 0);   // prefetch V chunk 0
            cp_commit();
            cp_wait1();
        }
        __syncthreads();

        const uint32_t qb = sb + ((hcb & 1) * 2) * AT_TILE;
        const uint32_t kb = qb + AT_TILE;
        #pragma unroll
        for (int ks = 0; ks < 8; ks++) {
            uint32_t qh[4];
            ldsm4(qh, qb + (wm * 16 + lr) * AT_PITCH + ks * 32 + lkb);
            #pragma unroll
            for (int p = 0; p < 2; p++) {
                uint32_t kh[4];
                ldsm4(kh, kb + (wn2 * 32 + p * 16 + lr) * AT_PITCH + ks * 32 + lkb);
                mma16816(sc[2 * p],     qh, kh[0], kh[2]);
                mma16816(sc[2 * p + 1], qh, kh[1], kh[3]);
            }
        }
        __syncthreads();
    }

    // ---- Softmax (rows R0 = wm*16 + lid>>2, R1 = R0+8; cross-warp via smem) ----
    const int R0 = wm * 16 + (lid >> 2);
    const int R1 = R0 + 8;
    const float scale = 0.04419417382415922f;   // 1/sqrt(512)
    float mx0 = -1e30f, mx1 = -1e30f;
    #pragma unroll
    for (int nf = 0; nf < 4; nf++) {
        #pragma unroll
        for (int q = 0; q < 4; q++) sc[nf][q] *= scale;
        mx0 = fmaxf(mx0, fmaxf(sc[nf][0], sc[nf][1]));
        mx1 = fmaxf(mx1, fmaxf(sc[nf][2], sc[nf][3]));
    }
    mx0 = fmaxf(mx0, __shfl_xor_sync(0xffffffffu, mx0, 1));
    mx0 = fmaxf(mx0, __shfl_xor_sync(0xffffffffu, mx0, 2));
    mx1 = fmaxf(mx1, __shfl_xor_sync(0xffffffffu, mx1, 1));
    mx1 = fmaxf(mx1, __shfl_xor_sync(0xffffffffu, mx1, 2));
    if ((lid & 3) == 0) {
        pmax[R0 * 2 + wn2] = mx0;
        pmax[R1 * 2 + wn2] = mx1;
    }
    __syncthreads();
    const float gm0 = fmaxf(pmax[R0 * 2], pmax[R0 * 2 + 1]);
    const float gm1 = fmaxf(pmax[R1 * 2], pmax[R1 * 2 + 1]);

    float s0 = 0.f, s1 = 0.f;
    #pragma unroll
    for (int nf = 0; nf < 4; nf++) {
        sc[nf][0] = __expf(sc[nf][0] - gm0); s0 += sc[nf][0];
        sc[nf][1] = __expf(sc[nf][1] - gm0); s0 += sc[nf][1];
        sc[nf][2] = __expf(sc[nf][2] - gm1); s1 += sc[nf][2];
        sc[nf][3] = __expf(sc[nf][3] - gm1); s1 += sc[nf][3];
    }
    s0 += __shfl_xor_sync(0xffffffffu, s0, 1);
    s0 += __shfl_xor_sync(0xffffffffu, s0, 2);
    s1 += __shfl_xor_sync(0xffffffffu, s1, 1);
    s1 += __shfl_xor_sync(0xffffffffu, s1, 2);
    if ((lid & 3) == 0) {
        psum[R0 * 2 + wn2] = s0;
        psum[R1 * 2 + wn2] = s1;
    }
    __syncthreads();
    const float inv0 = 1.f / (psum[R0 * 2] + psum[R0 * 2 + 1]);
    const float inv1 = 1.f / (psum[R1 * 2] + psum[R1 * 2 + 1]);

    // store P (fp16, row-major [row][token]) to smem for A-fragment exchange
    {
        char* Pp = smem + P_OFF;
        #pragma unroll
        for (int nf = 0; nf < 4; nf++) {
            const int col = wn2 * 32 + nf * 8 + (lid & 3) * 2;
            *(uint32_t*)(Pp + R0 * P_PITCH + col * 2) = packh2(sc[nf][0] * inv0, sc[nf][1] * inv0);
            *(uint32_t*)(Pp + R1 * P_PITCH + col * 2) = packh2(sc[nf][2] * inv1, sc[nf][3] * inv1);
        }
    }
    __syncthreads();

    // load P A-fragments (once; P static through phase 2)
    uint32_t pa[4][4];
    #pragma unroll
    for (int j = 0; j < 4; j++)
        ldsm4(pa[j], sb + P_OFF + (wm * 16 + lr) * P_PITCH + j * 32 + lkb);

    const int prow0 = perm[head * TLEN + R0];
    const int prow8 = perm[head * TLEN + R1];
    const size_t obase0 = ((size_t)b * SEQ + prow0) * HDIM;
    const size_t obase8 = ((size_t)b * SEQ + prow8) * HDIM;

    // ---- Phase 2: O = P V, double-buffered V staging (slots 0/1) ----
    for (int hcb = 0; hcb < 4; hcb++) {
        if (hcb < 3) {
            STAGE1(sb + ((hcb + 1) & 1) * AT_TILE, Vg, (hcb + 1) * 128);
            cp_commit();
            cp_wait1();
        } else {
            cp_wait0();
        }
        __syncthreads();

        const uint32_t vb = sb + (hcb & 1) * AT_TILE;
        float o[8][4];
        #pragma unroll
        for (int i = 0; i < 8; i++)
            #pragma unroll
            for (int q = 0; q < 4; q++) o[i][q] = 0.f;

        #pragma unroll
        for (int j = 0; j < 4; j++) {
            #pragma unroll
            for (int nf2 = 0; nf2 < 4; nf2++) {
                const uint32_t coff = (wn2 * 64 + nf2 * 16 + ((lid >> 4) & 1) * 8) * 2;
                uint32_t vh[4];
                ldsm4t(vh, vb + (j * 16 + lr) * AT_PITCH + coff);
                mma16816(o[2 * nf2],     pa[j], vh[0], vh[1]);
                mma16816(o[2 * nf2 + 1], pa[j], vh[2], vh[3]);
            }
        }

        const int hc = hcb * 128;
        #pragma unroll
        for (int nf = 0; nf < 8; nf++) {
            const int col = hc + wn2 * 64 + nf * 8 + (lid & 3) * 2;
            *(uint32_t*)(g_x16 + obase0 + col) = packh2(o[nf][0], o[nf][1]);
            *(uint32_t*)(g_x16 + obase8 + col) = packh2(o[nf][2], o[nf][3]);
        }
        __syncthreads();
    }
    #undef STAGE1
}

// ---------------------------------------------------------------------------
extern "C" void kernel_launch(void* const* d_in, const int* in_sizes, int n_in,
                              void* d_out, int out_size)
{
    const float* x  = (const float*)d_in[0];
    const float* Wq = (const float*)d_in[1];
    const float* bq = (const float*)d_in[2];
    const float* Wk = (const float*)d_in[3];
    const float* bk = (const float*)d_in[4];
    const float* Wv = (const float*)d_in[5];
    const float* bv = (const float*)d_in[6];
    const float* Wo = (const float*)d_in[7];
    const float* bo = (const float*)d_in[8];
    const int* perm = (const int*)d_in[9];
    float* out = (float*)d_out;

    __half *x16, *Wh, *qkv;
    cudaGetSymbolAddress((void**)&x16, g_x16);
    cudaGetSymbolAddress((void**)&Wh,  g_Wh);
    cudaGetSymbolAddress((void**)&qkv, g_QKV);

    cudaFuncSetAttribute(mma_gemm_kernel,
                         cudaFuncAttributeMaxDynamicSharedMemorySize, SMEM_REQ);
    cudaFuncSetAttribute(attn_kernel,
                         cudaFuncAttributeMaxDynamicSharedMemorySize, ATTN_SMEM);

    // all conversions in one launch
    conv_all_kernel<<<XB + 4 * WB, 256>>>(x, Wq, Wk, Wv, Wo, x16, Wh);

    // fused QKV projections (grid.z = 0..2) -> g_QKV fp16 (permuted rows)
    mma_gemm_kernel<<<dim3(HDIM / BN, NROWS / BM, 3), 256, SMEM_REQ>>>(
        x16, Wh, bq, bk, bv, nullptr, qkv, perm, 1);

    // tensorized attention -> g_x16 (fp16, un-permuted)
    attn_kernel<<<dim3(NHEAD, BATCH), 256, ATTN_SMEM>>>(perm);

    // output projection -> fp32 out
    mma_gemm_kernel<<<dim3(HDIM / BN, NROWS / BM, 1), 256, SMEM_REQ>>>(
        x16, Wh + 3 * (size_t)WN, bo, bo, bo, out, nullptr, perm, 0);
}

// round 10
// speedup vs baseline: 3.4024x; 1.0828x over previous
#include <cuda_runtime.h>
#include <cuda_fp16.h>
#include <cstdint>

#define BATCH 8
#define SEQ   4096
#define HDIM  512
#define NROWS (BATCH * SEQ)   // 32768
#define NHEAD 64
#define TLEN  64

#define BM 128
#define BN 128
#define BK 32
#define NCHUNK (HDIM / BK)    // 16
#define WN (HDIM * HDIM)

#define ROWB 80               // GEMM smem row stride bytes (32 fp16 + pad)

// GEMM smem layout: 3-stage A and B
#define SMP_PRM   0
#define SMP_A     512
#define SMP_B     (512 + 3 * 10240)
#define STG_STRIDE 10240
#define SMEM_REQ  (512 + 6 * 10240)        // 61952

// attn smem: 4 tile slots (64 rows x 272B) + P (64 x 144B) + reductions
#define AT_PITCH  272
#define AT_TILE   (64 * AT_PITCH)          // 17408
#define P_OFF     (4 * AT_TILE)            // 69632
#define P_PITCH   144
#define RED_OFF   (P_OFF + 64 * P_PITCH)   // 78848
#define ATTN_SMEM (RED_OFF + 1024)         // 79872

// conv grid split
#define XN4 ((NROWS * HDIM) / 4)           // 4194304
#define WN4 (WN / 4)                       // 65536
#define XB  (XN4 / 256)                    // 16384
#define WB  (WN4 / 256)                    // 256

// ---------------- scratch (device globals; allocation-free) ----------------
__device__ __half g_QKV[3 * NROWS * HDIM];   // Q, K, V (fp16, permuted order)
__device__ __half g_x16[NROWS * HDIM];       // fp16 activations (x, then attn out)
__device__ __half g_Wh[4 * HDIM * HDIM];     // fp16 weights

// ---------------- helpers ----------------
__device__ __forceinline__ uint32_t smem_to_u32(const void* p) {
    uint32_t a;
    asm("{ .reg .u64 t; cvta.to.shared.u64 t, %1; cvt.u32.u64 %0, t; }"
        : "=r"(a) : "l"(p));
    return a;
}
__device__ __forceinline__ void cp16(uint32_t dst, const void* src) {
    asm volatile("cp.async.cg.shared.global [%0], [%1], 16;"
                 :: "r"(dst), "l"(src) : "memory");
}
__device__ __forceinline__ void cp_commit() {
    asm volatile("cp.async.commit_group;" ::: "memory");
}
__device__ __forceinline__ void cp_wait1() {
    asm volatile("cp.async.wait_group 1;" ::: "memory");
}
__device__ __forceinline__ void cp_wait0() {
    asm volatile("cp.async.wait_group 0;" ::: "memory");
}
__device__ __forceinline__ void ldsm4(uint32_t* r, uint32_t addr) {
    asm volatile("ldmatrix.sync.aligned.m8n8.x4.shared.b16 {%0,%1,%2,%3}, [%4];"
                 : "=r"(r[0]), "=r"(r[1]), "=r"(r[2]), "=r"(r[3]) : "r"(addr));
}
__device__ __forceinline__ void ldsm4t(uint32_t* r, uint32_t addr) {
    asm volatile("ldmatrix.sync.aligned.m8n8.x4.trans.shared.b16 {%0,%1,%2,%3}, [%4];"
                 : "=r"(r[0]), "=r"(r[1]), "=r"(r[2]), "=r"(r[3]) : "r"(addr));
}
__device__ __forceinline__ void mma16816(float* d, const uint32_t* a,
                                         const uint32_t b0, const uint32_t b1) {
    asm volatile(
        "mma.sync.aligned.m16n8k16.row.col.f32.f16.f16.f32 "
        "{%0,%1,%2,%3}, {%4,%5,%6,%7}, {%8,%9}, {%0,%1,%2,%3};"
        : "+f"(d[0]), "+f"(d[1]), "+f"(d[2]), "+f"(d[3])
        : "r"(a[0]), "r"(a[1]), "r"(a[2]), "r"(a[3]), "r"(b0), "r"(b1));
}
__device__ __forceinline__ uint32_t packh2(float a, float b) {
    __half2 h = __floats2half2_rn(a, b);
    return *(uint32_t*)&h;
}

// ---------------------------------------------------------------------------
// fused conversion: x (XB blocks) then Wq,Wk,Wv,Wo (WB blocks each) -> fp16
// ---------------------------------------------------------------------------
__global__ void __launch_bounds__(256) conv_all_kernel(
    const float* __restrict__ x,
    const float* __restrict__ Wq, const float* __restrict__ Wk,
    const float* __restrict__ Wv, const float* __restrict__ Wo,
    __half* __restrict__ x16, __half* __restrict__ Wh)
{
    const int bid = blockIdx.x;
    const float* src;
    __half* dst;
    int i;
    if (bid < XB) {
        src = x; dst = x16; i = bid * 256 + threadIdx.x;
    } else {
        const int w = (bid - XB) / WB;
        const int lb = (bid - XB) - w * WB;
        src = (w == 0) ? Wq : (w == 1) ? Wk : (w == 2) ? Wv : Wo;
        dst = Wh + (size_t)w * WN;
        i = lb * 256 + threadIdx.x;
    }
    float4 v = ((const float4*)src)[i];
    uint2 o;
    o.x = packh2(v.x, v.y);
    o.y = packh2(v.z, v.w);
    ((uint2*)dst)[i] = o;
}

// ---------------------------------------------------------------------------
// single-product fp16 GEMM, 3-stage cp.async pipeline, 1 sync per chunk.
// out[m,n] = sum_k A[rowmap(m),k]*W[n,k] + bias[n]; blockIdx.z selects slice.
// ---------------------------------------------------------------------------
__global__ void __launch_bounds__(256, 2) mma_gemm_kernel(
    const __half* __restrict__ A16, const __half* __restrict__ Wbase,
    const float* __restrict__ b0p, const float* __restrict__ b1p,
    const float* __restrict__ b2p, float* __restrict__ outf,
    __half* __restrict__ outhBase, const int* __restrict__ perm, int use_perm)
{
    extern __shared__ char smem[];
    const uint32_t sb = smem_to_u32(smem);
    int* prm = (int*)(smem + SMP_PRM);

    const int z = blockIdx.z;
    const __half* Bh = Wbase + (size_t)z * WN;
    const float* bias = (z == 0) ? b0p : (z == 1) ? b1p : b2p;

    const int tid = threadIdx.x;
    const int lid = tid & 31;
    const int wid = tid >> 5;
    const int wm  = wid & 1;
    const int wn  = wid >> 1;

    const int n0 = blockIdx.x * BN;
    const int m0 = blockIdx.y * BM;
    const int b  = m0 / SEQ;
    const int i0 = m0 % SEQ;

    if (tid < BM)
        prm[tid] = b * SEQ + (use_perm ? perm[i0 + tid] : (i0 + tid));
    __syncthreads();

    const int r0 = tid >> 2;
    const int g  = tid & 3;
    const int pr0 = prm[r0];
    const int pr1 = prm[r0 + 64];
    const __half* sA0 = A16 + (size_t)pr0 * HDIM + g * 8;
    const __half* sA1 = A16 + (size_t)pr1 * HDIM + g * 8;
    const __half* sB0 = Bh + (size_t)(n0 + r0) * HDIM + g * 8;
    const __half* sB1 = Bh + (size_t)(n0 + r0 + 64) * HDIM + g * 8;
    const uint32_t d0 = (uint32_t)r0 * ROWB + g * 16;
    const uint32_t d1 = d0 + 64 * ROWB;

    const uint32_t lrow = (lid & 15);
    const uint32_t lk   = ((lid >> 4) & 1) * 16;
    const uint32_t aOff = (wm * 64 + lrow) * ROWB + lk;
    const uint32_t bOff = (wn * 32 + lrow) * ROWB + lk;

    float acc[4][4][4];
    #pragma unroll
    for (int i = 0; i < 4; i++)
        #pragma unroll
        for (int j = 0; j < 4; j++)
            #pragma unroll
            for (int q = 0; q < 4; q++) acc[i][j][q] = 0.f;

    #define GSTAGE(sidx, ko) do { \
        const uint32_t aB_ = sb + SMP_A + (sidx) * STG_STRIDE; \
        const uint32_t bB_ = sb + SMP_B + (sidx) * STG_STRIDE; \
        cp16(aB_ + d0, sA0 + (ko)); cp16(aB_ + d1, sA1 + (ko)); \
        cp16(bB_ + d0, sB0 + (ko)); cp16(bB_ + d1, sB1 + (ko)); \
    } while (0)

    // prologue: stage chunks 0 and 1
    GSTAGE(0, 0);           cp_commit();
    GSTAGE(1, (size_t)BK);  cp_commit();

    int rd = 0, wr = 2;
    for (int c = 0; c < NCHUNK; c++) {
        cp_wait1();          // chunk c resident (pending: c+1 [, c+2 empty-safe])
        __syncthreads();     // all warps done with chunk c-1 (buffer wr is free)

        // overlap: stage chunk c+2 while computing chunk c
        if (c + 2 < NCHUNK)
            GSTAGE(wr, (size_t)(c + 2) * BK);
        cp_commit();         // unconditional: keeps group accounting exact

        const uint32_t aB = sb + SMP_A + rd * STG_STRIDE;
        const uint32_t bB = sb + SMP_B + rd * STG_STRIDE;

        #pragma unroll
        for (int ks = 0; ks < 2; ks++) {
            uint32_t ah[4][4];
            #pragma unroll
            for (int mf = 0; mf < 4; mf++)
                ldsm4(ah[mf], aB + aOff + mf * (16 * ROWB) + ks * 32);
            #pragma unroll
            for (int p = 0; p < 2; p++) {
                uint32_t tb[4];
                ldsm4(tb, bB + bOff + p * (16 * ROWB) + ks * 32);
                #pragma unroll
                for (int mf = 0; mf < 4; mf++) {
                    mma16816(acc[mf][2 * p],     ah[mf], tb[0], tb[2]);
                    mma16816(acc[mf][2 * p + 1], ah[mf], tb[1], tb[3]);
                }
            }
        }
        rd = (rd + 1) % 3;
        wr = (wr + 1) % 3;
    }
    #undef GSTAGE

    // ---- epilogue ----
    __half* outh = outhBase ? (outhBase + (size_t)z * NROWS * HDIM) : nullptr;
    #pragma unroll
    for (int mf = 0; mf < 4; mf++) {
        const int row = m0 + wm * 64 + mf * 16 + (lid >> 2);
        #pragma unroll
        for (int nf = 0; nf < 4; nf++) {
            const int col = n0 + wn * 32 + nf * 8 + (lid & 3) * 2;
            const float2 bb = *(const float2*)(bias + col);
            float v00 = acc[mf][nf][0] + bb.x, v01 = acc[mf][nf][1] + bb.y;
            float v10 = acc[mf][nf][2] + bb.x, v11 = acc[mf][nf][3] + bb.y;
            if (outf) {
                *(float2*)(outf + (size_t)row * HDIM + col) = make_float2(v00, v01);
                *(float2*)(outf + (size_t)(row + 8) * HDIM + col) = make_float2(v10, v11);
            } else {
                *(uint32_t*)(outh + (size_t)row * HDIM + col)       = packh2(v00, v01);
                *(uint32_t*)(outh + (size_t)(row + 8) * HDIM + col) = packh2(v10, v11);
            }
        }
    }
}

// ---------------------------------------------------------------------------
// Tensorized block attention: 256 threads / 8 warps (unchanged from R9).
// ---------------------------------------------------------------------------
__global__ void __launch_bounds__(256) attn_kernel(const int* __restrict__ perm)
{
    extern __shared__ char smem[];
    const uint32_t sb = smem_to_u32(smem);
    float* red = (float*)(smem + RED_OFF);
    float* pmax = red;
    float* psum = red + 128;

    const int head = blockIdx.x;
    const int b    = blockIdx.y;
    const int tid  = threadIdx.x;
    const int lid  = tid & 31;
    const int wid  = tid >> 5;
    const int wm   = wid & 3;
    const int wn2  = wid >> 2;

    const size_t tokbase = ((size_t)b * SEQ + head * TLEN) * HDIM;
    const __half* Qg = g_QKV + 0 * (size_t)NROWS * HDIM + tokbase;
    const __half* Kg = g_QKV + 1 * (size_t)NROWS * HDIM + tokbase;
    const __half* Vg = g_QKV + 2 * (size_t)NROWS * HDIM + tokbase;

    const uint32_t lr = lid & 15;
    const uint32_t lkb = ((lid >> 4) & 1) * 16;

    #define STAGE1(dst, src, hc) do { \
        _Pragma("unroll") \
        for (int i_ = 0; i_ < 4; i_++) { \
            int idx_ = tid + i_ * 256; \
            int r_ = idx_ >> 4, cg_ = idx_ & 15; \
            cp16((dst) + r_ * AT_PITCH + cg_ * 16, (src) + (size_t)r_ * HDIM + (hc) + cg_ * 8); \
        } } while (0)

    float sc[4][4];
    #pragma unroll
    for (int i = 0; i < 4; i++)
        #pragma unroll
        for (int q = 0; q < 4; q++) sc[i][q] = 0.f;

    STAGE1(sb + 0 * AT_TILE, Qg, 0);
    STAGE1(sb + 1 * AT_TILE, Kg, 0);
    cp_commit();

    for (int hcb = 0; hcb < 4; hcb++) {
        if (hcb < 3) {
            const uint32_t s = ((hcb + 1) & 1) * 2;
            STAGE1(sb + s * AT_TILE, Qg, (hcb + 1) * 128);
            STAGE1(sb + (s + 1) * AT_TILE, Kg, (hcb + 1) * 128);
            cp_commit();
            cp_wait1();
        } else {
            STAGE1(sb + 0 * AT_TILE, Vg, 0);
            cp_commit();
            cp_wait1();
        }
        __syncthreads();

        const uint32_t qb = sb + ((hcb & 1) * 2) * AT_TILE;
        const uint32_t kb = qb + AT_TILE;
        #pragma unroll
        for (int ks = 0; ks < 8; ks++) {
            uint32_t qh[4];
            ldsm4(qh, qb + (wm * 16 + lr) * AT_PITCH + ks * 32 + lkb);
            #pragma unroll
            for (int p = 0; p < 2; p++) {
                uint32_t kh[4];
                ldsm4(kh, kb + (wn2 * 32 + p * 16 + lr) * AT_PITCH + ks * 32 + lkb);
                mma16816(sc[2 * p],     qh, kh[0], kh[2]);
                mma16816(sc[2 * p + 1], qh, kh[1], kh[3]);
            }
        }
        __syncthreads();
    }

    const int R0 = wm * 16 + (lid >> 2);
    const int R1 = R0 + 8;
    const float scale = 0.04419417382415922f;
    float mx0 = -1e30f, mx1 = -1e30f;
    #pragma unroll
    for (int nf = 0; nf < 4; nf++) {
        #pragma unroll
        for (int q = 0; q < 4; q++) sc[nf][q] *= scale;
        mx0 = fmaxf(mx0, fmaxf(sc[nf][0], sc[nf][1]));
        mx1 = fmaxf(mx1, fmaxf(sc[nf][2], sc[nf][3]));
    }
    mx0 = fmaxf(mx0, __shfl_xor_sync(0xffffffffu, mx0, 1));
    mx0 = fmaxf(mx0, __shfl_xor_sync(0xffffffffu, mx0, 2));
    mx1 = fmaxf(mx1, __shfl_xor_sync(0xffffffffu, mx1, 1));
    mx1 = fmaxf(mx1, __shfl_xor_sync(0xffffffffu, mx1, 2));
    if ((lid & 3) == 0) {
        pmax[R0 * 2 + wn2] = mx0;
        pmax[R1 * 2 + wn2] = mx1;
    }
    __syncthreads();
    const float gm0 = fmaxf(pmax[R0 * 2], pmax[R0 * 2 + 1]);
    const float gm1 = fmaxf(pmax[R1 * 2], pmax[R1 * 2 + 1]);

    float s0 = 0.f, s1 = 0.f;
    #pragma unroll
    for (int nf = 0; nf < 4; nf++) {
        sc[nf][0] = __expf(sc[nf][0] - gm0); s0 += sc[nf][0];
        sc[nf][1] = __expf(sc[nf][1] - gm0); s0 += sc[nf][1];
        sc[nf][2] = __expf(sc[nf][2] - gm1); s1 += sc[nf][2];
        sc[nf][3] = __expf(sc[nf][3] - gm1); s1 += sc[nf][3];
    }
    s0 += __shfl_xor_sync(0xffffffffu, s0, 1);
    s0 += __shfl_xor_sync(0xffffffffu, s0, 2);
    s1 += __shfl_xor_sync(0xffffffffu, s1, 1);
    s1 += __shfl_xor_sync(0xffffffffu, s1, 2);
    if ((lid & 3) == 0) {
        psum[R0 * 2 + wn2] = s0;
        psum[R1 * 2 + wn2] = s1;
    }
    __syncthreads();
    const float inv0 = 1.f / (psum[R0 * 2] + psum[R0 * 2 + 1]);
    const float inv1 = 1.f / (psum[R1 * 2] + psum[R1 * 2 + 1]);

    {
        char* Pp = smem + P_OFF;
        #pragma unroll
        for (int nf = 0; nf < 4; nf++) {
            const int col = wn2 * 32 + nf * 8 + (lid & 3) * 2;
            *(uint32_t*)(Pp + R0 * P_PITCH + col * 2) = packh2(sc[nf][0] * inv0, sc[nf][1] * inv0);
            *(uint32_t*)(Pp + R1 * P_PITCH + col * 2) = packh2(sc[nf][2] * inv1, sc[nf][3] * inv1);
        }
    }
    __syncthreads();

    uint32_t pa[4][4];
    #pragma unroll
    for (int j = 0; j < 4; j++)
        ldsm4(pa[j], sb + P_OFF + (wm * 16 + lr) * P_PITCH + j * 32 + lkb);

    const int prow0 = perm[head * TLEN + R0];
    const int prow8 = perm[head * TLEN + R1];
    const size_t obase0 = ((size_t)b * SEQ + prow0) * HDIM;
    const size_t obase8 = ((size_t)b * SEQ + prow8) * HDIM;

    for (int hcb = 0; hcb < 4; hcb++) {
        if (hcb < 3) {
            STAGE1(sb + ((hcb + 1) & 1) * AT_TILE, Vg, (hcb + 1) * 128);
            cp_commit();
            cp_wait1();
        } else {
            cp_wait0();
        }
        __syncthreads();

        const uint32_t vb = sb + (hcb & 1) * AT_TILE;
        float o[8][4];
        #pragma unroll
        for (int i = 0; i < 8; i++)
            #pragma unroll
            for (int q = 0; q < 4; q++) o[i][q] = 0.f;

        #pragma unroll
        for (int j = 0; j < 4; j++) {
            #pragma unroll
            for (int nf2 = 0; nf2 < 4; nf2++) {
                const uint32_t coff = (wn2 * 64 + nf2 * 16 + ((lid >> 4) & 1) * 8) * 2;
                uint32_t vh[4];
                ldsm4t(vh, vb + (j * 16 + lr) * AT_PITCH + coff);
                mma16816(o[2 * nf2],     pa[j], vh[0], vh[1]);
                mma16816(o[2 * nf2 + 1], pa[j], vh[2], vh[3]);
            }
        }

        const int hc = hcb * 128;
        #pragma unroll
        for (int nf = 0; nf < 8; nf++) {
            const int col = hc + wn2 * 64 + nf * 8 + (lid & 3) * 2;
            *(uint32_t*)(g_x16 + obase0 + col) = packh2(o[nf][0], o[nf][1]);
            *(uint32_t*)(g_x16 + obase8 + col) = packh2(o[nf][2], o[nf][3]);
        }
        __syncthreads();
    }
    #undef STAGE1
}

// ---------------------------------------------------------------------------
extern "C" void kernel_launch(void* const* d_in, const int* in_sizes, int n_in,
                              void* d_out, int out_size)
{
    const float* x  = (const float*)d_in[0];
    const float* Wq = (const float*)d_in[1];
    const float* bq = (const float*)d_in[2];
    const float* Wk = (const float*)d_in[3];
    const float* bk = (const float*)d_in[4];
    const float* Wv = (const float*)d_in[5];
    const float* bv = (const float*)d_in[6];
    const float* Wo = (const float*)d_in[7];
    const float* bo = (const float*)d_in[8];
    const int* perm = (const int*)d_in[9];
    float* out = (float*)d_out;

    __half *x16, *Wh, *qkv;
    cudaGetSymbolAddress((void**)&x16, g_x16);
    cudaGetSymbolAddress((void**)&Wh,  g_Wh);
    cudaGetSymbolAddress((void**)&qkv, g_QKV);

    cudaFuncSetAttribute(mma_gemm_kernel,
                         cudaFuncAttributeMaxDynamicSharedMemorySize, SMEM_REQ);
    cudaFuncSetAttribute(attn_kernel,
                         cudaFuncAttributeMaxDynamicSharedMemorySize, ATTN_SMEM);

    // all conversions in one launch
    conv_all_kernel<<<XB + 4 * WB, 256>>>(x, Wq, Wk, Wv, Wo, x16, Wh);

    // fused QKV projections (grid.z = 0..2) -> g_QKV fp16 (permuted rows)
    mma_gemm_kernel<<<dim3(HDIM / BN, NROWS / BM, 3), 256, SMEM_REQ>>>(
        x16, Wh, bq, bk, bv, nullptr, qkv, perm, 1);

    // tensorized attention -> g_x16 (fp16, un-permuted)
    attn_kernel<<<dim3(NHEAD, BATCH), 256, ATTN_SMEM>>>(perm);

    // output projection -> fp32 out
    mma_gemm_kernel<<<dim3(HDIM / BN, NROWS / BM, 1), 256, SMEM_REQ>>>(
        x16, Wh + 3 * (size_t)WN, bo, bo, bo, out, nullptr, perm, 0);
}

// round 11
// speedup vs baseline: 3.7326x; 1.0971x over previous
#include <cuda_runtime.h>
#include <cuda_fp16.h>
#include <cstdint>

#define BATCH 8
#define SEQ   4096
#define HDIM  512
#define NROWS (BATCH * SEQ)   // 32768
#define NHEAD 64
#define TLEN  64

#define BM 128
#define BN 128
#define BK 64
#define NCHUNK (HDIM / BK)    // 8
#define WN (HDIM * HDIM)

// GEMM smem: swizzled 128B rows, 3 stages of (A 16KB + B 16KB)
#define SMP_PRM    0
#define SMP_A      512
#define SMP_B      (512 + 3 * 16384)
#define STG_STRIDE 16384
#define SMEM_REQ   (512 + 6 * 16384)       // 98816

// attn smem: 4 tile slots (64 rows x 272B) + P (64 x 144B) + reductions
#define AT_PITCH  272
#define AT_TILE   (64 * AT_PITCH)          // 17408
#define P_OFF     (4 * AT_TILE)            // 69632
#define P_PITCH   144
#define RED_OFF   (P_OFF + 64 * P_PITCH)   // 78848
#define ATTN_SMEM (RED_OFF + 1024)         // 79872

// conv grid split
#define XN4 ((NROWS * HDIM) / 4)           // 4194304
#define WN4 (WN / 4)                       // 65536
#define XB  (XN4 / 256)                    // 16384
#define WB  (WN4 / 256)                    // 256

// ---------------- scratch (device globals; allocation-free) ----------------
__device__ __half g_QKV[3 * NROWS * HDIM];   // Q, K, V (fp16, permuted order)
__device__ __half g_x16[NROWS * HDIM];       // fp16 activations (x, then attn out)
__device__ __half g_Wh[4 * HDIM * HDIM];     // fp16 weights

// ---------------- helpers ----------------
__device__ __forceinline__ uint32_t smem_to_u32(const void* p) {
    uint32_t a;
    asm("{ .reg .u64 t; cvta.to.shared.u64 t, %1; cvt.u32.u64 %0, t; }"
        : "=r"(a) : "l"(p));
    return a;
}
__device__ __forceinline__ void cp16(uint32_t dst, const void* src) {
    asm volatile("cp.async.cg.shared.global [%0], [%1], 16;"
                 :: "r"(dst), "l"(src) : "memory");
}
__device__ __forceinline__ void cp_commit() {
    asm volatile("cp.async.commit_group;" ::: "memory");
}
__device__ __forceinline__ void cp_wait1() {
    asm volatile("cp.async.wait_group 1;" ::: "memory");
}
__device__ __forceinline__ void cp_wait0() {
    asm volatile("cp.async.wait_group 0;" ::: "memory");
}
__device__ __forceinline__ void ldsm4(uint32_t* r, uint32_t addr) {
    asm volatile("ldmatrix.sync.aligned.m8n8.x4.shared.b16 {%0,%1,%2,%3}, [%4];"
                 : "=r"(r[0]), "=r"(r[1]), "=r"(r[2]), "=r"(r[3]) : "r"(addr));
}
__device__ __forceinline__ void ldsm4t(uint32_t* r, uint32_t addr) {
    asm volatile("ldmatrix.sync.aligned.m8n8.x4.trans.shared.b16 {%0,%1,%2,%3}, [%4];"
                 : "=r"(r[0]), "=r"(r[1]), "=r"(r[2]), "=r"(r[3]) : "r"(addr));
}
__device__ __forceinline__ void mma16816(float* d, const uint32_t* a,
                                         const uint32_t b0, const uint32_t b1) {
    asm volatile(
        "mma.sync.aligned.m16n8k16.row.col.f32.f16.f16.f32 "
        "{%0,%1,%2,%3}, {%4,%5,%6,%7}, {%8,%9}, {%0,%1,%2,%3};"
        : "+f"(d[0]), "+f"(d[1]), "+f"(d[2]), "+f"(d[3])
        : "r"(a[0]), "r"(a[1]), "r"(a[2]), "r"(a[3]), "r"(b0), "r"(b1));
}
__device__ __forceinline__ uint32_t packh2(float a, float b) {
    __half2 h = __floats2half2_rn(a, b);
    return *(uint32_t*)&h;
}

// ---------------------------------------------------------------------------
// fused conversion: x (XB blocks) then Wq,Wk,Wv,Wo (WB blocks each) -> fp16
// ---------------------------------------------------------------------------
__global__ void __launch_bounds__(256) conv_all_kernel(
    const float* __restrict__ x,
    const float* __restrict__ Wq, const float* __restrict__ Wk,
    const float* __restrict__ Wv, const float* __restrict__ Wo,
    __half* __restrict__ x16, __half* __restrict__ Wh)
{
    const int bid = blockIdx.x;
    const float* src;
    __half* dst;
    int i;
    if (bid < XB) {
        src = x; dst = x16; i = bid * 256 + threadIdx.x;
    } else {
        const int w = (bid - XB) / WB;
        const int lb = (bid - XB) - w * WB;
        src = (w == 0) ? Wq : (w == 1) ? Wk : (w == 2) ? Wv : Wo;
        dst = Wh + (size_t)w * WN;
        i = lb * 256 + threadIdx.x;
    }
    float4 v = ((const float4*)src)[i];
    uint2 o;
    o.x = packh2(v.x, v.y);
    o.y = packh2(v.z, v.w);
    ((uint2*)dst)[i] = o;
}

// ---------------------------------------------------------------------------
// single-product fp16 GEMM, BK=64, swizzled smem, 3-stage cp.async pipeline,
// ONE __syncthreads per 64-wide chunk (8 per CTA total).
// out[m,n] = sum_k A[rowmap(m),k]*W[n,k] + bias[n]; blockIdx.z selects slice.
// ---------------------------------------------------------------------------
__global__ void __launch_bounds__(256, 2) mma_gemm_kernel(
    const __half* __restrict__ A16, const __half* __restrict__ Wbase,
    const float* __restrict__ b0p, const float* __restrict__ b1p,
    const float* __restrict__ b2p, float* __restrict__ outf,
    __half* __restrict__ outhBase, const int* __restrict__ perm, int use_perm)
{
    extern __shared__ char smem[];
    const uint32_t sb = smem_to_u32(smem);
    int* prm = (int*)(smem + SMP_PRM);

    const int z = blockIdx.z;
    const __half* Bh = Wbase + (size_t)z * WN;
    const float* bias = (z == 0) ? b0p : (z == 1) ? b1p : b2p;

    const int tid = threadIdx.x;
    const int lid = tid & 31;
    const int wid = tid >> 5;
    const int wm  = wid & 1;
    const int wn  = wid >> 1;

    const int n0 = blockIdx.x * BN;
    const int m0 = blockIdx.y * BM;
    const int b  = m0 / SEQ;
    const int i0 = m0 % SEQ;

    if (tid < BM)
        prm[tid] = b * SEQ + (use_perm ? perm[i0 + tid] : (i0 + tid));
    __syncthreads();

    // ---- staging setup: rows r0+32i (i=0..3), 16B chunk c of the 128B row ----
    const int r0 = tid >> 3;          // 0..31
    const int c  = tid & 7;           // 0..7
    const __half* aSrc[4];
    const __half* bSrc[4];
    #pragma unroll
    for (int i = 0; i < 4; i++) {
        aSrc[i] = A16 + (size_t)prm[r0 + 32 * i] * HDIM + c * 8;
        bSrc[i] = Bh + (size_t)(n0 + r0 + 32 * i) * HDIM + c * 8;
    }
    // swizzled dst offset: row*128 + ((c ^ (row&7))*16); row&7 invariant over i
    const uint32_t dsw = (uint32_t)r0 * 128 + (uint32_t)((c ^ (r0 & 7)) << 4);

    // ---- ldsm lane addressing (swizzled) ----
    const uint32_t lr  = (lid & 15);
    const uint32_t hib = (lid >> 4) & 1;       // 16B half of the 32B k-seg
    const uint32_t xr  = lr & 7;               // swizzle key (row&7)
    const uint32_t aRow = (wm * 64 + lr) * 128;
    const uint32_t bRow = (wn * 32 + lr) * 128;

    float acc[4][4][4];
    #pragma unroll
    for (int i = 0; i < 4; i++)
        #pragma unroll
        for (int j = 0; j < 4; j++)
            #pragma unroll
            for (int q = 0; q < 4; q++) acc[i][j][q] = 0.f;

    #define GSTAGE(sidx, ko) do { \
        const uint32_t aB_ = sb + SMP_A + (sidx) * STG_STRIDE; \
        const uint32_t bB_ = sb + SMP_B + (sidx) * STG_STRIDE; \
        _Pragma("unroll") \
        for (int i_ = 0; i_ < 4; i_++) { \
            cp16(aB_ + dsw + i_ * 4096, aSrc[i_] + (ko)); \
            cp16(bB_ + dsw + i_ * 4096, bSrc[i_] + (ko)); \
        } \
    } while (0)

    // prologue: stage chunks 0 and 1
    GSTAGE(0, 0);           cp_commit();
    GSTAGE(1, (size_t)BK);  cp_commit();

    int rd = 0, wr = 2;
    for (int ch = 0; ch < NCHUNK; ch++) {
        cp_wait1();          // chunk ch resident
        __syncthreads();     // buffer wr free (all warps past chunk ch-1)

        if (ch + 2 < NCHUNK)
            GSTAGE(wr, (size_t)(ch + 2) * BK);
        cp_commit();         // unconditional: exact group accounting

        const uint32_t aB = sb + SMP_A + rd * STG_STRIDE;
        const uint32_t bB = sb + SMP_B + rd * STG_STRIDE;

        #pragma unroll
        for (int ks = 0; ks < 4; ks++) {
            const uint32_t cc = ks * 2 + hib;
            const uint32_t sw = ((cc ^ xr) << 4);
            uint32_t ah[4][4];
            #pragma unroll
            for (int mf = 0; mf < 4; mf++)
                ldsm4(ah[mf], aB + aRow + mf * (16 * 128) + sw);
            #pragma unroll
            for (int p = 0; p < 2; p++) {
                uint32_t tb[4];
                ldsm4(tb, bB + bRow + p * (16 * 128) + sw);
                #pragma unroll
                for (int mf = 0; mf < 4; mf++) {
                    mma16816(acc[mf][2 * p],     ah[mf], tb[0], tb[2]);
                    mma16816(acc[mf][2 * p + 1], ah[mf], tb[1], tb[3]);
                }
            }
        }
        rd = (rd + 1) % 3;
        wr = (wr + 1) % 3;
    }
    #undef GSTAGE

    // ---- epilogue ----
    __half* outh = outhBase ? (outhBase + (size_t)z * NROWS * HDIM) : nullptr;
    #pragma unroll
    for (int mf = 0; mf < 4; mf++) {
        const int row = m0 + wm * 64 + mf * 16 + (lid >> 2);
        #pragma unroll
        for (int nf = 0; nf < 4; nf++) {
            const int col = n0 + wn * 32 + nf * 8 + (lid & 3) * 2;
            const float2 bb = *(const float2*)(bias + col);
            float v00 = acc[mf][nf][0] + bb.x, v01 = acc[mf][nf][1] + bb.y;
            float v10 = acc[mf][nf][2] + bb.x, v11 = acc[mf][nf][3] + bb.y;
            if (outf) {
                *(float2*)(outf + (size_t)row * HDIM + col) = make_float2(v00, v01);
                *(float2*)(outf + (size_t)(row + 8) * HDIM + col) = make_float2(v10, v11);
            } else {
                *(uint32_t*)(outh + (size_t)row * HDIM + col)       = packh2(v00, v01);
                *(uint32_t*)(outh + (size_t)(row + 8) * HDIM + col) = packh2(v10, v11);
            }
        }
    }
}

// ---------------------------------------------------------------------------
// Tensorized block attention: 256 threads / 8 warps (unchanged from R10).
// ---------------------------------------------------------------------------
__global__ void __launch_bounds__(256) attn_kernel(const int* __restrict__ perm)
{
    extern __shared__ char smem[];
    const uint32_t sb = smem_to_u32(smem);
    float* red = (float*)(smem + RED_OFF);
    float* pmax = red;
    float* psum = red + 128;

    const int head = blockIdx.x;
    const int b    = blockIdx.y;
    const int tid  = threadIdx.x;
    const int lid  = tid & 31;
    const int wid  = tid >> 5;
    const int wm   = wid & 3;
    const int wn2  = wid >> 2;

    const size_t tokbase = ((size_t)b * SEQ + head * TLEN) * HDIM;
    const __half* Qg = g_QKV + 0 * (size_t)NROWS * HDIM + tokbase;
    const __half* Kg = g_QKV + 1 * (size_t)NROWS * HDIM + tokbase;
    const __half* Vg = g_QKV + 2 * (size_t)NROWS * HDIM + tokbase;

    const uint32_t lr = lid & 15;
    const uint32_t lkb = ((lid >> 4) & 1) * 16;

    #define STAGE1(dst, src, hc) do { \
        _Pragma("unroll") \
        for (int i_ = 0; i_ < 4; i_++) { \
            int idx_ = tid + i_ * 256; \
            int r_ = idx_ >> 4, cg_ = idx_ & 15; \
            cp16((dst) + r_ * AT_PITCH + cg_ * 16, (src) + (size_t)r_ * HDIM + (hc) + cg_ * 8); \
        } } while (0)

    float sc[4][4];
    #pragma unroll
    for (int i = 0; i < 4; i++)
        #pragma unroll
        for (int q = 0; q < 4; q++) sc[i][q] = 0.f;

    STAGE1(sb + 0 * AT_TILE, Qg, 0);
    STAGE1(sb + 1 * AT_TILE, Kg, 0);
    cp_commit();

    for (int hcb = 0; hcb < 4; hcb++) {
        if (hcb < 3) {
            const uint32_t s = ((hcb + 1) & 1) * 2;
            STAGE1(sb + s * AT_TILE, Qg, (hcb + 1) * 128);
            STAGE1(sb + (s + 1) * AT_TILE, Kg, (hcb + 1) * 128);
            cp_commit();
            cp_wait1();
        } else {
            STAGE1(sb + 0 * AT_TILE, Vg, 0);
            cp_commit();
            cp_wait1();
        }
        __syncthreads();

        const uint32_t qb = sb + ((hcb & 1) * 2) * AT_TILE;
        const uint32_t kb = qb + AT_TILE;
        #pragma unroll
        for (int ks = 0; ks < 8; ks++) {
            uint32_t qh[4];
            ldsm4(qh, qb + (wm * 16 + lr) * AT_PITCH + ks * 32 + lkb);
            #pragma unroll
            for (int p = 0; p < 2; p++) {
                uint32_t kh[4];
                ldsm4(kh, kb + (wn2 * 32 + p * 16 + lr) * AT_PITCH + ks * 32 + lkb);
                mma16816(sc[2 * p],     qh, kh[0], kh[2]);
                mma16816(sc[2 * p + 1], qh, kh[1], kh[3]);
            }
        }
        __syncthreads();
    }

    const int R0 = wm * 16 + (lid >> 2);
    const int R1 = R0 + 8;
    const float scale = 0.04419417382415922f;
    float mx0 = -1e30f, mx1 = -1e30f;
    #pragma unroll
    for (int nf = 0; nf < 4; nf++) {
        #pragma unroll
        for (int q = 0; q < 4; q++) sc[nf][q] *= scale;
        mx0 = fmaxf(mx0, fmaxf(sc[nf][0], sc[nf][1]));
        mx1 = fmaxf(mx1, fmaxf(sc[nf][2], sc[nf][3]));
    }
    mx0 = fmaxf(mx0, __shfl_xor_sync(0xffffffffu, mx0, 1));
    mx0 = fmaxf(mx0, __shfl_xor_sync(0xffffffffu, mx0, 2));
    mx1 = fmaxf(mx1, __shfl_xor_sync(0xffffffffu, mx1, 1));
    mx1 = fmaxf(mx1, __shfl_xor_sync(0xffffffffu, mx1, 2));
    if ((lid & 3) == 0) {
        pmax[R0 * 2 + wn2] = mx0;
        pmax[R1 * 2 + wn2] = mx1;
    }
    __syncthreads();
    const float gm0 = fmaxf(pmax[R0 * 2], pmax[R0 * 2 + 1]);
    const float gm1 = fmaxf(pmax[R1 * 2], pmax[R1 * 2 + 1]);

    float s0 = 0.f, s1 = 0.f;
    #pragma unroll
    for (int nf = 0; nf < 4; nf++) {
        sc[nf][0] = __expf(sc[nf][0] - gm0); s0 += sc[nf][0];
        sc[nf][1] = __expf(sc[nf][1] - gm0); s0 += sc[nf][1];
        sc[nf][2] = __expf(sc[nf][2] - gm1); s1 += sc[nf][2];
        sc[nf][3] = __expf(sc[nf][3] - gm1); s1 += sc[nf][3];
    }
    s0 += __shfl_xor_sync(0xffffffffu, s0, 1);
    s0 += __shfl_xor_sync(0xffffffffu, s0, 2);
    s1 += __shfl_xor_sync(0xffffffffu, s1, 1);
    s1 += __shfl_xor_sync(0xffffffffu, s1, 2);
    if ((lid & 3) == 0) {
        psum[R0 * 2 + wn2] = s0;
        psum[R1 * 2 + wn2] = s1;
    }
    __syncthreads();
    const float inv0 = 1.f / (psum[R0 * 2] + psum[R0 * 2 + 1]);
    const float inv1 = 1.f / (psum[R1 * 2] + psum[R1 * 2 + 1]);

    {
        char* Pp = smem + P_OFF;
        #pragma unroll
        for (int nf = 0; nf < 4; nf++) {
            const int col = wn2 * 32 + nf * 8 + (lid & 3) * 2;
            *(uint32_t*)(Pp + R0 * P_PITCH + col * 2) = packh2(sc[nf][0] * inv0, sc[nf][1] * inv0);
            *(uint32_t*)(Pp + R1 * P_PITCH + col * 2) = packh2(sc[nf][2] * inv1, sc[nf][3] * inv1);
        }
    }
    __syncthreads();

    uint32_t pa[4][4];
    #pragma unroll
    for (int j = 0; j < 4; j++)
        ldsm4(pa[j], sb + P_OFF + (wm * 16 + lr) * P_PITCH + j * 32 + lkb);

    const int prow0 = perm[head * TLEN + R0];
    const int prow8 = perm[head * TLEN + R1];
    const size_t obase0 = ((size_t)b * SEQ + prow0) * HDIM;
    const size_t obase8 = ((size_t)b * SEQ + prow8) * HDIM;

    for (int hcb = 0; hcb < 4; hcb++) {
        if (hcb < 3) {
            STAGE1(sb + ((hcb + 1) & 1) * AT_TILE, Vg, (hcb + 1) * 128);
            cp_commit();
            cp_wait1();
        } else {
            cp_wait0();
        }
        __syncthreads();

        const uint32_t vb = sb + (hcb & 1) * AT_TILE;
        float o[8][4];
        #pragma unroll
        for (int i = 0; i < 8; i++)
            #pragma unroll
            for (int q = 0; q < 4; q++) o[i][q] = 0.f;

        #pragma unroll
        for (int j = 0; j < 4; j++) {
            #pragma unroll
            for (int nf2 = 0; nf2 < 4; nf2++) {
                const uint32_t coff = (wn2 * 64 + nf2 * 16 + ((lid >> 4) & 1) * 8) * 2;
                uint32_t vh[4];
                ldsm4t(vh, vb + (j * 16 + lr) * AT_PITCH + coff);
                mma16816(o[2 * nf2],     pa[j], vh[0], vh[1]);
                mma16816(o[2 * nf2 + 1], pa[j], vh[2], vh[3]);
            }
        }

        const int hc = hcb * 128;
        #pragma unroll
        for (int nf = 0; nf < 8; nf++) {
            const int col = hc + wn2 * 64 + nf * 8 + (lid & 3) * 2;
            *(uint32_t*)(g_x16 + obase0 + col) = packh2(o[nf][0], o[nf][1]);
            *(uint32_t*)(g_x16 + obase8 + col) = packh2(o[nf][2], o[nf][3]);
        }
        __syncthreads();
    }
    #undef STAGE1
}

// ---------------------------------------------------------------------------
extern "C" void kernel_launch(void* const* d_in, const int* in_sizes, int n_in,
                              void* d_out, int out_size)
{
    const float* x  = (const float*)d_in[0];
    const float* Wq = (const float*)d_in[1];
    const float* bq = (const float*)d_in[2];
    const float* Wk = (const float*)d_in[3];
    const float* bk = (const float*)d_in[4];
    const float* Wv = (const float*)d_in[5];
    const float* bv = (const float*)d_in[6];
    const float* Wo = (const float*)d_in[7];
    const float* bo = (const float*)d_in[8];
    const int* perm = (const int*)d_in[9];
    float* out = (float*)d_out;

    __half *x16, *Wh, *qkv;
    cudaGetSymbolAddress((void**)&x16, g_x16);
    cudaGetSymbolAddress((void**)&Wh,  g_Wh);
    cudaGetSymbolAddress((void**)&qkv, g_QKV);

    cudaFuncSetAttribute(mma_gemm_kernel,
                         cudaFuncAttributeMaxDynamicSharedMemorySize, SMEM_REQ);
    cudaFuncSetAttribute(attn_kernel,
                         cudaFuncAttributeMaxDynamicSharedMemorySize, ATTN_SMEM);

    // all conversions in one launch
    conv_all_kernel<<<XB + 4 * WB, 256>>>(x, Wq, Wk, Wv, Wo, x16, Wh);

    // fused QKV projections (grid.z = 0..2) -> g_QKV fp16 (permuted rows)
    mma_gemm_kernel<<<dim3(HDIM / BN, NROWS / BM, 3), 256, SMEM_REQ>>>(
        x16, Wh, bq, bk, bv, nullptr, qkv, perm, 1);

    // tensorized attention -> g_x16 (fp16, un-permuted)
    attn_kernel<<<dim3(NHEAD, BATCH), 256, ATTN_SMEM>>>(perm);

    // output projection -> fp32 out
    mma_gemm_kernel<<<dim3(HDIM / BN, NROWS / BM, 1), 256, SMEM_REQ>>>(
        x16, Wh + 3 * (size_t)WN, bo, bo, bo, out, nullptr, perm, 0);
}